// round 7
// baseline (speedup 1.0000x reference)
#include <cuda_runtime.h>
#include <math.h>

// Problem constants
#define DD    1024
#define KCLS  5
#define NSUP  5      // support per class
#define NQRY  75     // total queries (K*Q)
#define NAUG  40
#define NROWS 100    // 25 support + 75 queries
// hyperbolic constants: c = 0.01, sqrt(c) = 0.1

// ---------------- device scratch (static, no runtime alloc) ----------------
__device__ double g_P[NROWS * DD];     // projected Poincare points
__device__ double g_X2[NROWS];         // ||x||^2 per point
__device__ double g_KFAC[NROWS];       // 2/(1 + c||x||^2)
__device__ double g_LAM[NROWS];        // Lorentz factor of Klein point
__device__ int    g_PRED[NQRY];
__device__ double g_NLL[NQRY];
__device__ double g_M2[KCLS * DD];     // unnormalized refined Klein mean
__device__ double g_RDEN2[KCLS];       // 1/den2 for refined proto
__device__ double g_PX2B[KCLS];        // ||refined proto||^2

// ---------------- helpers ----------------
__device__ __forceinline__ double blk_reduce16(double v, double* sbuf) {
    #pragma unroll
    for (int o = 16; o > 0; o >>= 1) v += __shfl_down_sync(0xffffffffu, v, o);
    int w = threadIdx.x >> 5, l = threadIdx.x & 31;
    if (l == 0) sbuf[w] = v;
    __syncthreads();
    if (w == 0) {
        double r = (l < 16) ? sbuf[l] : 0.0;
        #pragma unroll
        for (int o = 16; o > 0; o >>= 1) r += __shfl_down_sync(0xffffffffu, r, o);
        if (l == 0) sbuf[0] = r;
    }
    __syncthreads();
    double r = sbuf[0];
    __syncthreads();
    return r;
}

__device__ __forceinline__ double blk_reduce32(double v, double* sbuf) {
    #pragma unroll
    for (int o = 16; o > 0; o >>= 1) v += __shfl_down_sync(0xffffffffu, v, o);
    int w = threadIdx.x >> 5, l = threadIdx.x & 31;
    if (l == 0) sbuf[w] = v;
    __syncthreads();
    if (w == 0) {
        double r = sbuf[l];
        #pragma unroll
        for (int o = 16; o > 0; o >>= 1) r += __shfl_down_sync(0xffffffffu, r, o);
        if (l == 0) sbuf[0] = r;
    }
    __syncthreads();
    double r = sbuf[0];
    __syncthreads();
    return r;
}

// Poincare distance given ||x||^2, ||y||^2, <x,y>  (c = 0.01)
__device__ __forceinline__ double hdist(double x2, double y2, double xy) {
    double a    = 1.0 - 0.02 * xy + 0.01 * y2;
    double b    = 1.0 - 0.01 * x2;
    double num2 = a * a * x2 + b * b * y2 - 2.0 * a * b * xy;
    double den  = fmax(1.0 - 0.02 * xy + 1e-4 * x2 * y2, 1e-5);
    double nrm  = sqrt(fmax(num2, 0.0)) / den;
    double z    = fmin(fmax(0.1 * nrm, -1.0 + 1e-5), 1.0 - 1e-5);
    return 20.0 * atanh(z);
}

// ---------------- K1: expmap0 + project + Klein scalars (100 rows) ----------------
__global__ void __launch_bounds__(512) k_transform(const float* __restrict__ feat) {
    __shared__ double sbuf[16];
    int row = blockIdx.x, tid = threadIdx.x;
    const float* u = feat + (size_t)row * DD;
    double uv0 = (double)u[tid], uv1 = (double)u[tid + 512];
    double s2 = blk_reduce16(uv0 * uv0 + uv1 * uv1, sbuf);

    double nrmu = sqrt(s2);
    double un   = fmax(nrmu, 1e-5);
    double s1   = tanh(0.1 * un) / (0.1 * un);
    double e0n  = s1 * nrmu;
    double nrm  = fmax(e0n, 1e-5);
    double s    = s1;
    if (nrm > 9.99) s = s1 * (9.99 / nrm);
    double x2 = s * s * s2;

    g_P[(size_t)row * DD + tid]       = s * uv0;
    g_P[(size_t)row * DD + tid + 512] = s * uv1;

    if (tid == 0) {
        g_X2[row] = x2;
        double kf = 2.0 / (1.0 + 0.01 * x2);
        double k2 = kf * kf * x2;
        g_KFAC[row] = kf;
        g_LAM[row]  = 1.0 / sqrt(fmax(1.0 - 0.01 * k2, 1e-5));
    }
}

// ---------------- K2: fused proto + dist + argmax + NLL (75 query blocks) ----------------
// Each block redundantly computes all 5 class Klein means (L2-resident reuse),
// reducing 5 mk2 + 5 dot values in one pass; protos never materialized.
__global__ void __launch_bounds__(512) k_protodist(const int* __restrict__ label) {
    __shared__ double sco[25];         // lam*kfac per support row
    __shared__ double srw[KCLS];       // 1/sum(lam) per class
    __shared__ double sred[16 * 10];
    __shared__ double sval[10];        // [0..4]=mk2, [5..9]=raw dot

    int q = blockIdx.x, tid = threadIdx.x;
    int w = tid >> 5, l = tid & 31;
    int row = 25 + q;

    if (tid < 25) sco[tid] = g_LAM[tid] * g_KFAC[tid];
    if (tid >= 32 && tid < 32 + KCLS) {
        int c = tid - 32;
        double ws = 0.0;
        for (int n = 0; n < NSUP; n++) ws += g_LAM[c * NSUP + n];
        srw[c] = 1.0 / ws;
    }
    __syncthreads();

    double x0 = g_P[(size_t)row * DD + tid];
    double x1 = g_P[(size_t)row * DD + tid + 512];

    double mk2p[KCLS], dotp[KCLS];
    #pragma unroll
    for (int c = 0; c < KCLS; c++) {
        double a0 = 0.0, a1 = 0.0;
        #pragma unroll
        for (int n = 0; n < NSUP; n++) {
            const double* Pp = &g_P[(size_t)(c * NSUP + n) * DD];
            a0 = fma(sco[c * NSUP + n], Pp[tid],       a0);
            a1 = fma(sco[c * NSUP + n], Pp[tid + 512], a1);
        }
        double m0 = a0 * srw[c], m1 = a1 * srw[c];
        mk2p[c] = m0 * m0 + m1 * m1;
        dotp[c] = x0 * m0 + x1 * m1;
    }
    #pragma unroll
    for (int c = 0; c < KCLS; c++) {
        double v = mk2p[c], u = dotp[c];
        #pragma unroll
        for (int o = 16; o > 0; o >>= 1) {
            v += __shfl_down_sync(0xffffffffu, v, o);
            u += __shfl_down_sync(0xffffffffu, u, o);
        }
        if (l == 0) { sred[w * 10 + c] = v; sred[w * 10 + 5 + c] = u; }
    }
    __syncthreads();
    if (tid < 10) {
        double r = 0.0;
        #pragma unroll
        for (int ww = 0; ww < 16; ww++) r += sred[ww * 10 + tid];
        sval[tid] = r;
    }
    __syncthreads();

    if (tid == 0) {
        double x2 = g_X2[row];
        double dist[KCLS];
        int best = 0; double bd = 1e300;
        #pragma unroll
        for (int c = 0; c < KCLS; c++) {
            double mk2 = sval[c];
            double den = 1.0 + sqrt(fmax(1.0 - 0.01 * mk2, 0.0));  // k2p
            double px2 = mk2 / (den * den);
            double xy  = sval[5 + c] / den;
            dist[c] = hdist(x2, px2, xy);
            if (dist[c] < bd) { bd = dist[c]; best = c; }
        }
        g_PRED[q] = best;
        double m = -1e300;
        #pragma unroll
        for (int c = 0; c < KCLS; c++) m = fmax(m, -dist[c]);
        double se = 0.0;
        #pragma unroll
        for (int c = 0; c < KCLS; c++) se += exp(-dist[c] - m);
        double lse = m + log(se);
        int lbl = label[NQRY + q];
        g_NLL[q] = lse + dist[lbl];   // log_softmax(log_softmax(x)) == log_softmax(x)
    }
}

// ---------------- K3: per-class fused stats + aug-rows + refined proto (5 blocks x 1024) ----------------
__global__ void __launch_bounds__(1024) k_classDEF(const float* __restrict__ feat,
                                                   const float* __restrict__ noise) {
    __shared__ double sMKD[DD], sSTD[DD];
    __shared__ double sme[80], slam[80], scoef[80];
    __shared__ int    srow[80];
    __shared__ double sCA[NAUG], sCB[NAUG], sWL2[NAUG];
    __shared__ double sbuf[32];
    __shared__ double s_rw, s_cnt, s_wsup;
    __shared__ int    s_m;
    __shared__ double s_rw2, s_SA;

    int c = blockIdx.x, tid = threadIdx.x;
    int w = tid >> 5, l = tid & 31;
    int d = tid;   // one dim per thread

    // ---- masks + compaction ----
    if (tid < 80) {
        int row; double mm;
        if (tid < NSUP) { row = c * NSUP + tid; mm = 1.0; }
        else            { row = 25 + (tid - NSUP); mm = (g_PRED[tid - NSUP] == c) ? 1.0 : 0.0; }
        sme[tid]   = mm;
        srow[tid]  = row;
        double lm  = g_LAM[row];
        slam[tid]  = lm;
        scoef[tid] = lm * g_KFAC[row];
    }
    __syncthreads();
    if (tid == 0) {
        double wsup = 0.0;
        for (int n = 0; n < NSUP; n++) wsup += slam[n];
        s_wsup = wsup;
        double wsum = 0.0, cn = 0.0; int m = 0;
        for (int p = 0; p < 80; p++) {
            if (sme[p] != 0.0) {
                wsum += slam[p]; cn += 1.0;
                srow[m] = srow[p]; scoef[m] = scoef[p]; m++;
            }
        }
        s_rw = 1.0 / wsum; s_cnt = cn; s_m = m;
    }
    __syncthreads();
    int m = s_m;
    double cnt = s_cnt, rw = s_rw;

    // ---- Phase D: masked Klein mean + Euclid std per dim (4-way ILP) ----
    double ak[4] = {0,0,0,0}, ae[4] = {0,0,0,0}, ae2[4] = {0,0,0,0};
    int ji = 0;
    for (; ji + 3 < m; ji += 4) {
        #pragma unroll
        for (int k = 0; k < 4; k++) {
            int row   = srow[ji + k];
            double Pv = g_P[(size_t)row * DD + d];
            double Ev = (double)feat[(size_t)row * DD + d];
            ak[k]  = fma(scoef[ji + k], Pv, ak[k]);
            ae[k]  += Ev;
            ae2[k] = fma(Ev, Ev, ae2[k]);
        }
    }
    for (; ji < m; ji++) {
        int row   = srow[ji];
        double Pv = g_P[(size_t)row * DD + d];
        double Ev = (double)feat[(size_t)row * DD + d];
        ak[0]  = fma(scoef[ji], Pv, ak[0]);
        ae[0]  += Ev;
        ae2[0] = fma(Ev, Ev, ae2[0]);
    }
    double AK  = (ak[0]  + ak[1])  + (ak[2]  + ak[3]);
    double AE  = (ae[0]  + ae[1])  + (ae[2]  + ae[3]);
    double AE2 = (ae2[0] + ae2[1]) + (ae2[2] + ae2[3]);

    double mkd = AK * rw;
    sMKD[d] = mkd;
    double var = fmax(AE2 - AE * AE / cnt, 0.0) / (cnt - 1.0);
    sSTD[d] = sqrt(var);

    double mk2 = blk_reduce32(mkd * mkd, sbuf);   // includes syncthreads (sMKD/sSTD published)
    double den   = 1.0 + sqrt(fmax(1.0 - 0.01 * mk2, 0.0));
    double rden  = 1.0 / den;
    double x2sp  = mk2 / (den * den);
    double ptfac = 1.0 - 0.01 * x2sp;
    double lamx  = 2.0 / fmax(1.0 - 0.01 * x2sp, 1e-5);

    // ---- Phase E: one warp per aug row ----
    for (int j = w; j < NAUG; j += 32) {
        const float* nz = noise + ((size_t)(c * NAUG + j)) * DD;
        double a2a = 0.0, a2b = 0.0, ada = 0.0, adb = 0.0;
        #pragma unroll
        for (int i = 0; i < 32; i += 2) {
            int d0 = l + i * 32, d1 = l + (i + 1) * 32;
            double w0 = (double)nz[d0] * sSTD[d0];
            double w1 = (double)nz[d1] * sSTD[d1];
            a2a = fma(w0, w0, a2a);
            a2b = fma(w1, w1, a2b);
            ada = fma(sMKD[d0], w0, ada);
            adb = fma(sMKD[d1], w1, adb);
        }
        double a2v = a2a + a2b, adv = ada + adb;
        #pragma unroll
        for (int o = 16; o > 0; o >>= 1) {
            a2v += __shfl_down_sync(0xffffffffu, a2v, o);
            adv += __shfl_down_sync(0xffffffffu, adv, o);
        }
        if (l == 0) {
            double pt2 = ptfac * ptfac * a2v;
            double dxp = ptfac * rden * adv;
            double un  = fmax(sqrt(pt2), 1e-5);
            double t   = tanh(0.05 * lamx * un) / (0.1 * un);
            double y2  = t * t * pt2;
            double xy  = t * dxp;
            double A   = 1.0 + 0.02 * xy + 0.01 * y2;
            double B   = ptfac * t;
            double dn  = fmax(1.0 + 0.02 * xy + 1e-4 * x2sp * y2, 1e-5);
            double ex2 = (A * A * x2sp + B * B * pt2 + 2.0 * A * B * dxp) / (dn * dn);
            double kf  = 2.0 / (1.0 + 0.01 * ex2);
            double k2  = kf * kf * ex2;
            double lm  = 1.0 / sqrt(fmax(1.0 - 0.01 * k2, 1e-5));
            sCA[j]  = lm * kf * A / dn;
            sCB[j]  = lm * kf * B / dn;
            sWL2[j] = lm;
        }
    }
    __syncthreads();

    // ---- Phase F: refined prototype per dim ----
    if (tid == 0) {
        double w2 = s_wsup, sa = 0.0;
        for (int j = 0; j < NAUG; j++) { w2 += sWL2[j]; sa += sCA[j]; }
        s_rw2 = 1.0 / w2; s_SA = sa;
    }
    __syncthreads();

    double acc = 0.0;
    #pragma unroll
    for (int n = 0; n < NSUP; n++)
        acc = fma(scoef[n], g_P[(size_t)(c * NSUP + n) * DD + d], acc);  // supports = first 5 compacted
    acc += s_SA * (sMKD[d] * rden);

    double nA[4] = {0,0,0,0};
    #pragma unroll
    for (int j = 0; j < NAUG; j += 4) {
        #pragma unroll
        for (int k = 0; k < 4; k++)
            nA[k] = fma(sCB[j + k], (double)noise[((size_t)(c * NAUG + j + k)) * DD + d], nA[k]);
    }
    double AN = (nA[0] + nA[1]) + (nA[2] + nA[3]);
    acc += AN * ptfac * sSTD[d];

    double m2 = acc * s_rw2;
    g_M2[(size_t)c * DD + d] = m2;
    double mk2b = blk_reduce32(m2 * m2, sbuf);
    if (tid == 0) {
        double den2 = 1.0 + sqrt(fmax(1.0 - 0.01 * mk2b, 0.0));
        g_RDEN2[c] = 1.0 / den2;
        g_PX2B[c]  = mk2b / (den2 * den2);
    }
}

// ---------------- K4: dist_new -> softmax y_pred; block 75 reduces loss ----------------
__global__ void __launch_bounds__(512) k_final(float* __restrict__ out) {
    __shared__ double sred[16 * KCLS];
    __shared__ double sdots[KCLS];
    int q = blockIdx.x, tid = threadIdx.x;
    int w = tid >> 5, l = tid & 31;

    if (q == NQRY) {
        if (tid == 0) {
            double ssum = 0.0;
            for (int i = 0; i < NQRY; i++) ssum += g_NLL[i];
            out[NQRY * KCLS] = (float)(ssum / (double)NQRY);
        }
        return;
    }

    int row = 25 + q;
    double x0 = g_P[(size_t)row * DD + tid];
    double x1 = g_P[(size_t)row * DD + tid + 512];
    double p5[KCLS];
    #pragma unroll
    for (int j = 0; j < KCLS; j++)
        p5[j] = x0 * g_M2[(size_t)j * DD + tid] + x1 * g_M2[(size_t)j * DD + tid + 512];
    #pragma unroll
    for (int j = 0; j < KCLS; j++) {
        double v = p5[j];
        #pragma unroll
        for (int o = 16; o > 0; o >>= 1) v += __shfl_down_sync(0xffffffffu, v, o);
        if (l == 0) sred[w * KCLS + j] = v;
    }
    __syncthreads();
    if (tid < KCLS) {
        double r = 0.0;
        #pragma unroll
        for (int ww = 0; ww < 16; ww++) r += sred[ww * KCLS + tid];
        sdots[tid] = r;
    }
    __syncthreads();

    if (tid == 0) {
        double x2 = g_X2[row];
        double dist[KCLS];
        double m = -1e300;
        #pragma unroll
        for (int j = 0; j < KCLS; j++) {
            dist[j] = hdist(x2, g_PX2B[j], sdots[j] * g_RDEN2[j]);
            m = fmax(m, -dist[j]);
        }
        double e[KCLS]; double se = 0.0;
        #pragma unroll
        for (int j = 0; j < KCLS; j++) { e[j] = exp(-dist[j] - m); se += e[j]; }
        #pragma unroll
        for (int j = 0; j < KCLS; j++) out[q * KCLS + j] = (float)(e[j] / se);
    }
}

// ---------------- launch ----------------
extern "C" void kernel_launch(void* const* d_in, const int* in_sizes, int n_in,
                              void* d_out, int out_size) {
    const float* feat  = (const float*)d_in[0];
    const int*   label = (const int*)  d_in[1];
    const float* noise = (const float*)d_in[2];
    float* out = (float*)d_out;

    k_transform<<<NROWS, 512>>>(feat);
    k_protodist<<<NQRY, 512>>>(label);
    k_classDEF<<<KCLS, 1024>>>(feat, noise);
    k_final<<<NQRY + 1, 512>>>(out);
}

// round 8
// speedup vs baseline: 1.5717x; 1.5717x over previous
#include <cuda_runtime.h>
#include <math.h>

// Problem constants
#define DD    1024
#define KCLS  5
#define NSUP  5      // support per class
#define NQRY  75     // total queries (K*Q)
#define NAUG  40
#define NROWS 100    // 25 support + 75 queries
#define NSEGS 16     // stats: per-class dim segments (16*64 = 1024)
#define NSEG  8      // augnew: per-class dim segments (8*128 = 1024)
// hyperbolic constants: c = 0.01, sqrt(c) = 0.1

// ---------------- device scratch (static, no runtime alloc) ----------------
__device__ double g_P[NROWS * DD];       // projected Poincare points
__device__ double g_X2[NROWS];           // ||x||^2 per point
__device__ double g_KFAC[NROWS];         // 2/(1 + c||x||^2)
__device__ double g_LAM[NROWS];          // Lorentz factor of Klein point
__device__ double g_PROTO[KCLS * DD];    // initial prototypes
__device__ double g_PX2[KCLS];
__device__ int    g_PRED[NQRY];
__device__ double g_NLL[NQRY];
__device__ double g_MKD[KCLS * DD];      // masked Klein mean per dim
__device__ double g_STD[KCLS * DD];      // per-dim std of masked Euclid pts
__device__ double g_MK2P[KCLS * NSEGS];  // partial sums of mkd^2 (16/class)
__device__ double g_M2[KCLS * DD];       // unnormalized refined Klein mean
__device__ double g_MK2BP[KCLS * NSEG];  // partial sums of m2^2 (8/class)

// ---------------- helpers ----------------
__device__ __forceinline__ double blk_reduce(double v, double* sbuf, int nwarps) {
    #pragma unroll
    for (int o = 16; o > 0; o >>= 1) v += __shfl_down_sync(0xffffffffu, v, o);
    int w = threadIdx.x >> 5, l = threadIdx.x & 31;
    if (l == 0) sbuf[w] = v;
    __syncthreads();
    if (w == 0) {
        double r = (l < nwarps) ? sbuf[l] : 0.0;
        #pragma unroll
        for (int o = 16; o > 0; o >>= 1) r += __shfl_down_sync(0xffffffffu, r, o);
        if (l == 0) sbuf[0] = r;
    }
    __syncthreads();
    double r = sbuf[0];
    __syncthreads();
    return r;
}

// Poincare distance given ||x||^2, ||y||^2, <x,y>  (c = 0.01)
__device__ __forceinline__ double hdist(double x2, double y2, double xy) {
    double a    = 1.0 - 0.02 * xy + 0.01 * y2;
    double b    = 1.0 - 0.01 * x2;
    double num2 = a * a * x2 + b * b * y2 - 2.0 * a * b * xy;
    double den  = fmax(1.0 - 0.02 * xy + 1e-4 * x2 * y2, 1e-5);
    double nrm  = sqrt(fmax(num2, 0.0)) / den;
    double z    = fmin(fmax(0.1 * nrm, -1.0 + 1e-5), 1.0 - 1e-5);
    return 20.0 * atanh(z);
}

// ---------------- K1: expmap0 + project + Klein scalars (100 rows) ----------------
__global__ void k_transform(const float* __restrict__ feat) {
    __shared__ double sbuf[8];
    int row = blockIdx.x, tid = threadIdx.x;
    const float* u = feat + (size_t)row * DD;
    double uv[4];
    double s2 = 0.0;
    #pragma unroll
    for (int i = 0; i < 4; i++) { uv[i] = (double)u[tid + i * 256]; s2 += uv[i] * uv[i]; }
    s2 = blk_reduce(s2, sbuf, 8);

    double nrmu = sqrt(s2);
    double un   = fmax(nrmu, 1e-5);
    double s1   = tanh(0.1 * un) / (0.1 * un);
    double e0n  = s1 * nrmu;
    double nrm  = fmax(e0n, 1e-5);
    double s    = s1;
    if (nrm > 9.99) s = s1 * (9.99 / nrm);
    double x2 = s * s * s2;

    #pragma unroll
    for (int i = 0; i < 4; i++)
        g_P[(size_t)row * DD + tid + i * 256] = s * uv[i];

    if (tid == 0) {
        g_X2[row] = x2;
        double kf = 2.0 / (1.0 + 0.01 * x2);
        double k2 = kf * kf * x2;
        g_KFAC[row] = kf;
        g_LAM[row]  = 1.0 / sqrt(fmax(1.0 - 0.01 * k2, 1e-5));
    }
}

// ---------------- K2: initial prototypes (5 classes) ----------------
__global__ void k_proto() {
    __shared__ double sco[NSUP];
    __shared__ double srw;
    __shared__ double sbuf[8];
    int c = blockIdx.x, tid = threadIdx.x;
    if (tid < NSUP) sco[tid] = g_LAM[c * NSUP + tid] * g_KFAC[c * NSUP + tid];
    if (tid == 0) {
        double w = 0.0;
        for (int n = 0; n < NSUP; n++) w += g_LAM[c * NSUP + n];
        srw = 1.0 / w;
    }
    __syncthreads();
    double rwsum = srw;

    double mk[4]; double part = 0.0;
    #pragma unroll
    for (int i = 0; i < 4; i++) {
        int d = tid + i * 256;
        double a = 0.0;
        #pragma unroll
        for (int n = 0; n < NSUP; n++) a += sco[n] * g_P[(size_t)(c * NSUP + n) * DD + d];
        mk[i] = a * rwsum;
        part += mk[i] * mk[i];
    }
    double mk2 = blk_reduce(part, sbuf, 8);
    double den = 1.0 + sqrt(fmax(1.0 - 0.01 * mk2, 0.0));   // k2p
    double rden = 1.0 / den;
    #pragma unroll
    for (int i = 0; i < 4; i++)
        g_PROTO[(size_t)c * DD + tid + i * 256] = mk[i] * rden;
    if (tid == 0) g_PX2[c] = mk2 / (den * den);
}

// ---------------- K3: dist matrix, argmax pred, per-query NLL (75 queries) ----------------
__global__ void k_dist1(const int* __restrict__ label) {
    __shared__ double sred[8 * KCLS];
    __shared__ double sdots[KCLS];
    int q = blockIdx.x, tid = threadIdx.x;
    int row = 25 + q;
    int w = tid >> 5, l = tid & 31;

    double p5[KCLS] = {0.0, 0.0, 0.0, 0.0, 0.0};
    #pragma unroll
    for (int i = 0; i < 4; i++) {
        int d = tid + i * 256;
        double xv = g_P[(size_t)row * DD + d];
        #pragma unroll
        for (int j = 0; j < KCLS; j++) p5[j] += xv * g_PROTO[(size_t)j * DD + d];
    }
    #pragma unroll
    for (int j = 0; j < KCLS; j++) {
        double v = p5[j];
        #pragma unroll
        for (int o = 16; o > 0; o >>= 1) v += __shfl_down_sync(0xffffffffu, v, o);
        if (l == 0) sred[w * KCLS + j] = v;
    }
    __syncthreads();
    if (tid < KCLS) {
        double r = 0.0;
        #pragma unroll
        for (int ww = 0; ww < 8; ww++) r += sred[ww * KCLS + tid];
        sdots[tid] = r;
    }
    __syncthreads();

    if (tid == 0) {
        double x2 = g_X2[row];
        double dist[KCLS];
        int best = 0; double bd = 1e300;
        #pragma unroll
        for (int j = 0; j < KCLS; j++) {
            dist[j] = hdist(x2, g_PX2[j], sdots[j]);
            if (dist[j] < bd) { bd = dist[j]; best = j; }
        }
        g_PRED[q] = best;
        double m = -1e300;
        #pragma unroll
        for (int j = 0; j < KCLS; j++) m = fmax(m, -dist[j]);
        double se = 0.0;
        #pragma unroll
        for (int j = 0; j < KCLS; j++) se += exp(-dist[j] - m);
        double lse = m + log(se);
        int lbl = label[NQRY + q];
        g_NLL[q] = lse + dist[lbl];   // log_softmax(log_softmax(x)) == log_softmax(x)
    }
}

// ---------------- K4: per-class per-dim masked Klein mean + Euclid std ----------------
// grid = KCLS * NSEGS = 80 blocks, 512 threads = 8 point-groups x 64 dims.
// Compacted active-row list; per-thread serial rows ~m/8 (short latency chain).
__global__ void __launch_bounds__(512) k_stats(const float* __restrict__ feat) {
    __shared__ double sme[80], slam[80], scoef[80];
    __shared__ int    srow[80];
    __shared__ double s_ak[8][64], s_ae[8][64], s_ae2[8][64];
    __shared__ double s_m2[64];
    __shared__ double s_rw, s_cnt;
    __shared__ int    s_m;

    int c = blockIdx.x >> 4, s = blockIdx.x & 15;
    int tid  = threadIdx.x;
    int g    = tid >> 6;          // point-group 0..7
    int lane = tid & 63;          // dim within segment
    int d    = s * 64 + lane;

    if (tid < 80) {
        int row; double mm;
        if (tid < NSUP) { row = c * NSUP + tid; mm = 1.0; }
        else            { row = 25 + (tid - NSUP); mm = (g_PRED[tid - NSUP] == c) ? 1.0 : 0.0; }
        sme[tid]   = mm;
        srow[tid]  = row;
        double lm  = g_LAM[row];
        slam[tid]  = lm;
        scoef[tid] = lm * g_KFAC[row];
    }
    __syncthreads();
    if (tid == 0) {
        double wsum = 0.0, cn = 0.0; int m = 0;
        for (int p = 0; p < 80; p++) {
            if (sme[p] != 0.0) {
                wsum += slam[p]; cn += 1.0;
                srow[m] = srow[p]; scoef[m] = scoef[p]; m++;
            }
        }
        s_rw = 1.0 / wsum; s_cnt = cn; s_m = m;
    }
    __syncthreads();
    int m = s_m;

    double ak = 0.0, ae = 0.0, ae2 = 0.0;
    #pragma unroll 4
    for (int ji = g; ji < m; ji += 8) {
        int row   = srow[ji];
        double Pv = g_P[(size_t)row * DD + d];
        double Ev = (double)feat[(size_t)row * DD + d];
        ak  = fma(scoef[ji], Pv, ak);
        ae  += Ev;
        ae2 = fma(Ev, Ev, ae2);
    }
    s_ak[g][lane] = ak; s_ae[g][lane] = ae; s_ae2[g][lane] = ae2;
    __syncthreads();

    if (g == 0) {
        double AK = 0.0, AE = 0.0, AE2 = 0.0;
        #pragma unroll
        for (int gg = 0; gg < 8; gg++) {
            AK += s_ak[gg][lane]; AE += s_ae[gg][lane]; AE2 += s_ae2[gg][lane];
        }
        double cnt = s_cnt;
        double mkd = AK * s_rw;
        g_MKD[(size_t)c * DD + d] = mkd;
        double var = fmax(AE2 - AE * AE / cnt, 0.0) / (cnt - 1.0);
        g_STD[(size_t)c * DD + d] = sqrt(var);
        s_m2[lane] = mkd * mkd;
    }
    __syncthreads();
    if (tid == 0) {
        double part = 0.0;
        for (int i = 0; i < 64; i++) part += s_m2[i];
        g_MK2P[c * NSEGS + s] = part;
    }
}

// ---------------- K5: fused aug-row coefficients + refined prototype ----------------
// grid = KCLS * NSEG = 40 blocks, 512 threads. Each block:
//  - loads class MKD/STD into smem (16 KB)
//  - computes ALL 40 aug-row coefficients warp-parallel (8x redundant, cheap)
//  - per-dim refined proto for its 128-dim segment (4 row-groups x 128 dims)
__global__ void __launch_bounds__(512) k_augnew(const float* __restrict__ noise) {
    __shared__ double sMKD[DD], sSTD[DD];
    __shared__ double sCA[NAUG], sCB[NAUG], sWL2[NAUG];
    __shared__ double sco[NSUP];
    __shared__ double s_accN[4][128], s_m2s[128];
    __shared__ double s_rden, s_x2sp, s_ptfac, s_lamx, s_wsup;
    __shared__ double s_rw2, s_SA;

    int c = blockIdx.x >> 3, s = blockIdx.x & 7;
    int tid = threadIdx.x;
    int w = tid >> 5, l = tid & 31;

    // load class MKD/STD (2 dims per thread)
    sMKD[tid]       = g_MKD[(size_t)c * DD + tid];
    sMKD[tid + 512] = g_MKD[(size_t)c * DD + tid + 512];
    sSTD[tid]       = g_STD[(size_t)c * DD + tid];
    sSTD[tid + 512] = g_STD[(size_t)c * DD + tid + 512];
    if (tid < NSUP) sco[tid] = g_LAM[c * NSUP + tid] * g_KFAC[c * NSUP + tid];
    if (tid == 0) {
        double mk2 = 0.0;
        for (int t = 0; t < NSEGS; t++) mk2 += g_MK2P[c * NSEGS + t];
        double den = 1.0 + sqrt(fmax(1.0 - 0.01 * mk2, 0.0));
        double x2sp = mk2 / (den * den);
        s_rden  = 1.0 / den;
        s_x2sp  = x2sp;
        s_ptfac = 1.0 - 0.01 * x2sp;
        s_lamx  = 2.0 / fmax(1.0 - 0.01 * x2sp, 1e-5);
        double wsup = 0.0;
        for (int n = 0; n < NSUP; n++) wsup += g_LAM[c * NSUP + n];
        s_wsup = wsup;
    }
    __syncthreads();
    double rden = s_rden, x2sp = s_x2sp, ptfac = s_ptfac, lamx = s_lamx;

    // ---- all 40 row coefficients, one warp per row ----
    for (int j = w; j < NAUG; j += 16) {
        const float* nz = noise + ((size_t)(c * NAUG + j)) * DD;
        double a2a = 0.0, a2b = 0.0, ada = 0.0, adb = 0.0;
        #pragma unroll
        for (int i = 0; i < 32; i += 2) {
            int d0 = l + i * 32, d1 = l + (i + 1) * 32;
            double w0 = (double)nz[d0] * sSTD[d0];
            double w1 = (double)nz[d1] * sSTD[d1];
            a2a = fma(w0, w0, a2a);
            a2b = fma(w1, w1, a2b);
            ada = fma(sMKD[d0], w0, ada);
            adb = fma(sMKD[d1], w1, adb);
        }
        double a2v = a2a + a2b, adv = ada + adb;
        #pragma unroll
        for (int o = 16; o > 0; o >>= 1) {
            a2v += __shfl_down_sync(0xffffffffu, a2v, o);
            adv += __shfl_down_sync(0xffffffffu, adv, o);
        }
        if (l == 0) {
            double pt2 = ptfac * ptfac * a2v;
            double dxp = ptfac * rden * adv;
            double un  = fmax(sqrt(pt2), 1e-5);
            double t   = tanh(0.05 * lamx * un) / (0.1 * un);
            double y2  = t * t * pt2;
            double xy  = t * dxp;
            double A   = 1.0 + 0.02 * xy + 0.01 * y2;
            double B   = ptfac * t;
            double dn  = fmax(1.0 + 0.02 * xy + 1e-4 * x2sp * y2, 1e-5);
            double ex2 = (A * A * x2sp + B * B * pt2 + 2.0 * A * B * dxp) / (dn * dn);
            double kf  = 2.0 / (1.0 + 0.01 * ex2);
            double k2  = kf * kf * ex2;
            double lm  = 1.0 / sqrt(fmax(1.0 - 0.01 * k2, 1e-5));
            sCA[j]  = lm * kf * A / dn;
            sCB[j]  = lm * kf * B / dn;
            sWL2[j] = lm;
        }
    }
    __syncthreads();
    if (tid == 0) {
        double w2 = s_wsup, sa = 0.0;
        for (int j = 0; j < NAUG; j++) { w2 += sWL2[j]; sa += sCA[j]; }
        s_rw2 = 1.0 / w2; s_SA = sa;
    }
    __syncthreads();

    // ---- per-dim refined proto for segment s (4 groups x 128 dims) ----
    int g2   = tid >> 7;
    int lane = tid & 127;
    int d    = s * 128 + lane;

    double accN = 0.0;
    #pragma unroll
    for (int ji = 0; ji < 10; ji++) {
        int j = g2 * 10 + ji;
        accN = fma(sCB[j], (double)noise[((size_t)(c * NAUG + j)) * DD + d], accN);
    }
    s_accN[g2][lane] = accN;
    __syncthreads();

    if (g2 == 0) {
        double acc = 0.0;
        #pragma unroll
        for (int n = 0; n < NSUP; n++)
            acc = fma(sco[n], g_P[(size_t)(c * NSUP + n) * DD + d], acc);
        acc += s_SA * (sMKD[d] * rden);
        double AN = (s_accN[0][lane] + s_accN[1][lane]) + (s_accN[2][lane] + s_accN[3][lane]);
        acc += AN * ptfac * sSTD[d];

        double m2 = acc * s_rw2;
        g_M2[(size_t)c * DD + d] = m2;
        s_m2s[lane] = m2 * m2;
    }
    __syncthreads();
    if (tid == 0) {
        double part = 0.0;
        for (int i = 0; i < 128; i++) part += s_m2s[i];
        g_MK2BP[c * NSEG + s] = part;
    }
}

// ---------------- K6: dist_new -> softmax y_pred; block 75 reduces loss ----------------
__global__ void k_final(float* __restrict__ out) {
    __shared__ double sred[8 * KCLS];
    __shared__ double sdots[KCLS];
    __shared__ double sden2[KCLS], sy2[KCLS];
    int q = blockIdx.x, tid = threadIdx.x;
    int w = tid >> 5, l = tid & 31;

    if (q == NQRY) {
        if (tid == 0) {
            double ssum = 0.0;
            for (int i = 0; i < NQRY; i++) ssum += g_NLL[i];
            out[NQRY * KCLS] = (float)(ssum / (double)NQRY);
        }
        return;
    }

    if (tid < KCLS) {
        double mk2b = 0.0;
        for (int s = 0; s < NSEG; s++) mk2b += g_MK2BP[tid * NSEG + s];
        double den2 = 1.0 + sqrt(fmax(1.0 - 0.01 * mk2b, 0.0));
        sden2[tid] = den2;
        sy2[tid]   = mk2b / (den2 * den2);
    }

    int row = 25 + q;
    double p5[KCLS] = {0.0, 0.0, 0.0, 0.0, 0.0};
    #pragma unroll
    for (int i = 0; i < 4; i++) {
        int d = tid + i * 256;
        double xv = g_P[(size_t)row * DD + d];
        #pragma unroll
        for (int j = 0; j < KCLS; j++) p5[j] += xv * g_M2[(size_t)j * DD + d];
    }
    #pragma unroll
    for (int j = 0; j < KCLS; j++) {
        double v = p5[j];
        #pragma unroll
        for (int o = 16; o > 0; o >>= 1) v += __shfl_down_sync(0xffffffffu, v, o);
        if (l == 0) sred[w * KCLS + j] = v;
    }
    __syncthreads();
    if (tid < KCLS) {
        double r = 0.0;
        #pragma unroll
        for (int ww = 0; ww < 8; ww++) r += sred[ww * KCLS + tid];
        sdots[tid] = r;
    }
    __syncthreads();

    if (tid == 0) {
        double x2 = g_X2[row];
        double dist[KCLS];
        double m = -1e300;
        #pragma unroll
        for (int j = 0; j < KCLS; j++) {
            dist[j] = hdist(x2, sy2[j], sdots[j] / sden2[j]);
            m = fmax(m, -dist[j]);
        }
        double e[KCLS]; double se = 0.0;
        #pragma unroll
        for (int j = 0; j < KCLS; j++) { e[j] = exp(-dist[j] - m); se += e[j]; }
        #pragma unroll
        for (int j = 0; j < KCLS; j++) out[q * KCLS + j] = (float)(e[j] / se);
    }
}

// ---------------- launch ----------------
extern "C" void kernel_launch(void* const* d_in, const int* in_sizes, int n_in,
                              void* d_out, int out_size) {
    const float* feat  = (const float*)d_in[0];
    const int*   label = (const int*)  d_in[1];
    const float* noise = (const float*)d_in[2];
    float* out = (float*)d_out;

    k_transform<<<NROWS, 256>>>(feat);
    k_proto<<<KCLS, 256>>>();
    k_dist1<<<NQRY, 256>>>(label);
    k_stats<<<KCLS * NSEGS, 512>>>(feat);
    k_augnew<<<KCLS * NSEG, 512>>>(noise);
    k_final<<<NQRY + 1, 256>>>(out);
}

// round 9
// speedup vs baseline: 2.6683x; 1.6977x over previous
#include <cuda_runtime.h>
#include <math.h>

// Problem constants
#define DD    1024
#define KCLS  5
#define NSUP  5      // support per class
#define NQRY  75     // total queries (K*Q)
#define NAUG  40
#define NROWS 100    // 25 support + 75 queries
#define NSEGS 16     // stats: per-class dim segments (16*64 = 1024)
#define NSEG  8      // newproto: per-class dim segments (8*128 = 1024)
// hyperbolic constants: c = 0.01, sqrt(c) = 0.1

// ---------------- device scratch (static, no runtime alloc) ----------------
__device__ double g_P[NROWS * DD];       // projected Poincare points
__device__ double g_X2[NROWS];           // ||x||^2 per point
__device__ double g_KFAC[NROWS];         // 2/(1 + c||x||^2)
__device__ double g_LAM[NROWS];          // Lorentz factor of Klein point
__device__ double g_PROTO[KCLS * DD];    // initial prototypes
__device__ double g_PX2[KCLS];
__device__ int    g_PRED[NQRY];
__device__ double g_NLL[NQRY];
__device__ double g_MKD[KCLS * DD];      // masked Klein mean per dim
__device__ double g_STD[KCLS * DD];      // per-dim std of masked Euclid pts
__device__ double g_MK2P[KCLS * NSEGS];  // partial sums of mkd^2 (16/class)
__device__ double g_CA[KCLS * NAUG];     // per-aug-row coefficient on s_p
__device__ double g_CB[KCLS * NAUG];     // per-aug-row coefficient on noise
__device__ double g_WL2[KCLS * NAUG];    // per-aug-row Lorentz weight
__device__ double g_M2[KCLS * DD];       // unnormalized refined Klein mean
__device__ double g_MK2BP[KCLS * NSEG];  // partial sums of m2^2 (8/class)

// ---------------- helpers ----------------
__device__ __forceinline__ double blk_reduce(double v, double* sbuf, int nwarps) {
    #pragma unroll
    for (int o = 16; o > 0; o >>= 1) v += __shfl_down_sync(0xffffffffu, v, o);
    int w = threadIdx.x >> 5, l = threadIdx.x & 31;
    if (l == 0) sbuf[w] = v;
    __syncthreads();
    if (w == 0) {
        double r = (l < nwarps) ? sbuf[l] : 0.0;
        #pragma unroll
        for (int o = 16; o > 0; o >>= 1) r += __shfl_down_sync(0xffffffffu, r, o);
        if (l == 0) sbuf[0] = r;
    }
    __syncthreads();
    double r = sbuf[0];
    __syncthreads();
    return r;
}

// Poincare distance given ||x||^2, ||y||^2, <x,y>  (c = 0.01)
__device__ __forceinline__ double hdist(double x2, double y2, double xy) {
    double a    = 1.0 - 0.02 * xy + 0.01 * y2;
    double b    = 1.0 - 0.01 * x2;
    double num2 = a * a * x2 + b * b * y2 - 2.0 * a * b * xy;
    double den  = fmax(1.0 - 0.02 * xy + 1e-4 * x2 * y2, 1e-5);
    double nrm  = sqrt(fmax(num2, 0.0)) / den;
    double z    = fmin(fmax(0.1 * nrm, -1.0 + 1e-5), 1.0 - 1e-5);
    return 20.0 * atanh(z);
}

// ---------------- K1: expmap0 + project + Klein scalars (100 rows) ----------------
__global__ void k_transform(const float* __restrict__ feat) {
    __shared__ double sbuf[8];
    int row = blockIdx.x, tid = threadIdx.x;
    const float* u = feat + (size_t)row * DD;
    double uv[4];
    double s2 = 0.0;
    #pragma unroll
    for (int i = 0; i < 4; i++) { uv[i] = (double)u[tid + i * 256]; s2 += uv[i] * uv[i]; }
    s2 = blk_reduce(s2, sbuf, 8);

    double nrmu = sqrt(s2);
    double un   = fmax(nrmu, 1e-5);
    double s1   = tanh(0.1 * un) / (0.1 * un);
    double e0n  = s1 * nrmu;
    double nrm  = fmax(e0n, 1e-5);
    double s    = s1;
    if (nrm > 9.99) s = s1 * (9.99 / nrm);
    double x2 = s * s * s2;

    #pragma unroll
    for (int i = 0; i < 4; i++)
        g_P[(size_t)row * DD + tid + i * 256] = s * uv[i];

    if (tid == 0) {
        g_X2[row] = x2;
        double kf = 2.0 / (1.0 + 0.01 * x2);
        double k2 = kf * kf * x2;
        g_KFAC[row] = kf;
        g_LAM[row]  = 1.0 / sqrt(fmax(1.0 - 0.01 * k2, 1e-5));
    }
}

// ---------------- K2: initial prototypes (5 classes) ----------------
__global__ void k_proto() {
    __shared__ double sco[NSUP];
    __shared__ double srw;
    __shared__ double sbuf[8];
    int c = blockIdx.x, tid = threadIdx.x;
    if (tid < NSUP) sco[tid] = g_LAM[c * NSUP + tid] * g_KFAC[c * NSUP + tid];
    if (tid == 0) {
        double w = 0.0;
        for (int n = 0; n < NSUP; n++) w += g_LAM[c * NSUP + n];
        srw = 1.0 / w;
    }
    __syncthreads();
    double rwsum = srw;

    double mk[4]; double part = 0.0;
    #pragma unroll
    for (int i = 0; i < 4; i++) {
        int d = tid + i * 256;
        double a = 0.0;
        #pragma unroll
        for (int n = 0; n < NSUP; n++) a += sco[n] * g_P[(size_t)(c * NSUP + n) * DD + d];
        mk[i] = a * rwsum;
        part += mk[i] * mk[i];
    }
    double mk2 = blk_reduce(part, sbuf, 8);
    double den = 1.0 + sqrt(fmax(1.0 - 0.01 * mk2, 0.0));   // k2p
    double rden = 1.0 / den;
    #pragma unroll
    for (int i = 0; i < 4; i++)
        g_PROTO[(size_t)c * DD + tid + i * 256] = mk[i] * rden;
    if (tid == 0) g_PX2[c] = mk2 / (den * den);
}

// ---------------- K3: dist matrix, argmax pred, per-query NLL (75 queries) ----------------
__global__ void k_dist1(const int* __restrict__ label) {
    __shared__ double sred[8 * KCLS];
    __shared__ double sdots[KCLS];
    int q = blockIdx.x, tid = threadIdx.x;
    int row = 25 + q;
    int w = tid >> 5, l = tid & 31;

    double p5[KCLS] = {0.0, 0.0, 0.0, 0.0, 0.0};
    #pragma unroll
    for (int i = 0; i < 4; i++) {
        int d = tid + i * 256;
        double xv = g_P[(size_t)row * DD + d];
        #pragma unroll
        for (int j = 0; j < KCLS; j++) p5[j] += xv * g_PROTO[(size_t)j * DD + d];
    }
    #pragma unroll
    for (int j = 0; j < KCLS; j++) {
        double v = p5[j];
        #pragma unroll
        for (int o = 16; o > 0; o >>= 1) v += __shfl_down_sync(0xffffffffu, v, o);
        if (l == 0) sred[w * KCLS + j] = v;
    }
    __syncthreads();
    if (tid < KCLS) {
        double r = 0.0;
        #pragma unroll
        for (int ww = 0; ww < 8; ww++) r += sred[ww * KCLS + tid];
        sdots[tid] = r;
    }
    __syncthreads();

    if (tid == 0) {
        double x2 = g_X2[row];
        double dist[KCLS];
        int best = 0; double bd = 1e300;
        #pragma unroll
        for (int j = 0; j < KCLS; j++) {
            dist[j] = hdist(x2, g_PX2[j], sdots[j]);
            if (dist[j] < bd) { bd = dist[j]; best = j; }
        }
        g_PRED[q] = best;
        double m = -1e300;
        #pragma unroll
        for (int j = 0; j < KCLS; j++) m = fmax(m, -dist[j]);
        double se = 0.0;
        #pragma unroll
        for (int j = 0; j < KCLS; j++) se += exp(-dist[j] - m);
        double lse = m + log(se);
        int lbl = label[NQRY + q];
        g_NLL[q] = lse + dist[lbl];   // log_softmax(log_softmax(x)) == log_softmax(x)
    }
}

// ---------------- K4: per-class per-dim masked Klein mean + Euclid std ----------------
// grid = KCLS * NSEGS = 80 blocks, 512 threads = 8 point-groups x 64 dims.
__global__ void __launch_bounds__(512) k_stats(const float* __restrict__ feat) {
    __shared__ double sme[80], slam[80], scoef[80];
    __shared__ int    srow[80];
    __shared__ double s_ak[8][64], s_ae[8][64], s_ae2[8][64];
    __shared__ double s_m2[64];
    __shared__ double s_rw, s_cnt;
    __shared__ int    s_m;

    int c = blockIdx.x >> 4, s = blockIdx.x & 15;
    int tid  = threadIdx.x;
    int g    = tid >> 6;          // point-group 0..7
    int lane = tid & 63;          // dim within segment
    int d    = s * 64 + lane;

    if (tid < 80) {
        int row; double mm;
        if (tid < NSUP) { row = c * NSUP + tid; mm = 1.0; }
        else            { row = 25 + (tid - NSUP); mm = (g_PRED[tid - NSUP] == c) ? 1.0 : 0.0; }
        sme[tid]   = mm;
        srow[tid]  = row;
        double lm  = g_LAM[row];
        slam[tid]  = lm;
        scoef[tid] = lm * g_KFAC[row];
    }
    __syncthreads();
    if (tid == 0) {
        double wsum = 0.0, cn = 0.0; int m = 0;
        for (int p = 0; p < 80; p++) {
            if (sme[p] != 0.0) {
                wsum += slam[p]; cn += 1.0;
                srow[m] = srow[p]; scoef[m] = scoef[p]; m++;
            }
        }
        s_rw = 1.0 / wsum; s_cnt = cn; s_m = m;
    }
    __syncthreads();
    int m = s_m;

    double ak = 0.0, ae = 0.0, ae2 = 0.0;
    #pragma unroll 4
    for (int ji = g; ji < m; ji += 8) {
        int row   = srow[ji];
        double Pv = g_P[(size_t)row * DD + d];
        double Ev = (double)feat[(size_t)row * DD + d];
        ak  = fma(scoef[ji], Pv, ak);
        ae  += Ev;
        ae2 = fma(Ev, Ev, ae2);
    }
    s_ak[g][lane] = ak; s_ae[g][lane] = ae; s_ae2[g][lane] = ae2;
    __syncthreads();

    if (g == 0) {
        double AK = 0.0, AE = 0.0, AE2 = 0.0;
        #pragma unroll
        for (int gg = 0; gg < 8; gg++) {
            AK += s_ak[gg][lane]; AE += s_ae[gg][lane]; AE2 += s_ae2[gg][lane];
        }
        double cnt = s_cnt;
        double mkd = AK * s_rw;
        g_MKD[(size_t)c * DD + d] = mkd;
        double var = fmax(AE2 - AE * AE / cnt, 0.0) / (cnt - 1.0);
        g_STD[(size_t)c * DD + d] = sqrt(var);
        s_m2[lane] = mkd * mkd;
    }
    __syncthreads();
    if (tid == 0) {
        double part = 0.0;
        for (int i = 0; i < 64; i++) part += s_m2[i];
        g_MK2P[c * NSEGS + s] = part;
    }
}

// ---------------- K5: per (class, aug-row): pt reductions + scalar chain ----------------
// grid = KCLS * NAUG = 200 blocks, 256 threads. Scalars hoisted out of the per-dim loop.
__global__ void k_augrow(const float* __restrict__ noise) {
    __shared__ double sred[8 * 2];
    __shared__ double s_rden, s_x2sp, s_ptfac;

    int c = blockIdx.x / NAUG, j = blockIdx.x % NAUG;
    int tid = threadIdx.x;
    int w = tid >> 5, l = tid & 31;

    if (tid == 0) {
        double mk2 = 0.0;
        for (int s = 0; s < NSEGS; s++) mk2 += g_MK2P[c * NSEGS + s];
        double den = 1.0 + sqrt(fmax(1.0 - 0.01 * mk2, 0.0));
        s_rden  = 1.0 / den;
        double x2sp = mk2 / (den * den);
        s_x2sp  = x2sp;
        s_ptfac = 1.0 - 0.01 * x2sp;
    }
    __syncthreads();
    double rden = s_rden, x2sp = s_x2sp, ptfac = s_ptfac;

    const float* nz = noise + ((size_t)(c * NAUG + j)) * DD;
    double a2 = 0.0, ad = 0.0;
    #pragma unroll
    for (int i = 0; i < 4; i++) {
        int dd = tid + i * 256;
        double wv = (double)nz[dd] * g_STD[(size_t)c * DD + dd];
        a2 = fma(wv, wv, a2);
        ad = fma(g_MKD[(size_t)c * DD + dd], wv, ad);
    }
    #pragma unroll
    for (int o = 16; o > 0; o >>= 1) {
        a2 += __shfl_down_sync(0xffffffffu, a2, o);
        ad += __shfl_down_sync(0xffffffffu, ad, o);
    }
    if (l == 0) { sred[w * 2] = a2; sred[w * 2 + 1] = ad; }
    __syncthreads();

    if (tid == 0) {
        double A2 = 0.0, AD = 0.0;
        #pragma unroll
        for (int ww = 0; ww < 8; ww++) { A2 += sred[ww * 2]; AD += sred[ww * 2 + 1]; }
        double pt2 = ptfac * ptfac * A2;
        double dxp = ptfac * rden * AD;

        double lamx = 2.0 / fmax(1.0 - 0.01 * x2sp, 1e-5);
        double un  = fmax(sqrt(pt2), 1e-5);
        double t   = tanh(0.05 * lamx * un) / (0.1 * un);
        double y2  = t * t * pt2;
        double xy  = t * dxp;
        double A   = 1.0 + 0.02 * xy + 0.01 * y2;
        double B   = ptfac * t;
        double dn  = fmax(1.0 + 0.02 * xy + 1e-4 * x2sp * y2, 1e-5);
        double ex2 = (A * A * x2sp + B * B * pt2 + 2.0 * A * B * dxp) / (dn * dn);
        double kf  = 2.0 / (1.0 + 0.01 * ex2);
        double k2  = kf * kf * ex2;
        double lm  = 1.0 / sqrt(fmax(1.0 - 0.01 * k2, 1e-5));
        g_CA[c * NAUG + j]  = lm * kf * A / dn;
        g_CB[c * NAUG + j]  = lm * kf * B / dn;
        g_WL2[c * NAUG + j] = lm;
    }
}

// ---------------- K6: refined prototype per dim (unnormalized Klein mean) ----------------
// grid = KCLS * NSEG = 40 blocks, 512 threads = 4 row-groups x 128 dims.
__global__ void __launch_bounds__(512) k_newproto(const float* __restrict__ noise) {
    __shared__ double scb[NAUG], sco[NSUP];
    __shared__ double s_accN[4][128];
    __shared__ double s_m2s[128];
    __shared__ double s_rwsum2, s_SA, s_ptfac, s_rden;

    int c = blockIdx.x >> 3, s = blockIdx.x & 7;
    int tid  = threadIdx.x;
    int g    = tid >> 7;
    int lane = tid & 127;
    int d    = s * 128 + lane;

    if (tid < NAUG) scb[tid] = g_CB[c * NAUG + tid];
    if (tid >= 64 && tid < 64 + NSUP) sco[tid - 64] = g_LAM[c * NSUP + tid - 64] * g_KFAC[c * NSUP + tid - 64];
    if (tid == 0) {
        double mk2 = 0.0;
        for (int t = 0; t < NSEGS; t++) mk2 += g_MK2P[c * NSEGS + t];
        double den = 1.0 + sqrt(fmax(1.0 - 0.01 * mk2, 0.0));
        double x2sp = mk2 / (den * den);
        s_rden  = 1.0 / den;
        s_ptfac = 1.0 - 0.01 * x2sp;
        double w2 = 0.0, sa = 0.0;
        for (int n = 0; n < NSUP; n++) w2 += g_LAM[c * NSUP + n];
        for (int j = 0; j < NAUG; j++) { w2 += g_WL2[c * NAUG + j]; sa += g_CA[c * NAUG + j]; }
        s_rwsum2 = 1.0 / w2; s_SA = sa;
    }
    __syncthreads();

    double accN = 0.0;
    #pragma unroll
    for (int ji = 0; ji < 10; ji++) {
        int j = g * 10 + ji;
        accN = fma(scb[j], (double)noise[((size_t)(c * NAUG + j)) * DD + d], accN);
    }
    s_accN[g][lane] = accN;
    __syncthreads();

    if (g == 0) {
        double acc = 0.0;
        #pragma unroll
        for (int n = 0; n < NSUP; n++)
            acc = fma(sco[n], g_P[(size_t)(c * NSUP + n) * DD + d], acc);
        double spd = g_MKD[(size_t)c * DD + d] * s_rden;
        acc += s_SA * spd;
        double AN = s_accN[0][lane] + s_accN[1][lane] + s_accN[2][lane] + s_accN[3][lane];
        acc += AN * s_ptfac * g_STD[(size_t)c * DD + d];

        double m2 = acc * s_rwsum2;
        g_M2[(size_t)c * DD + d] = m2;
        s_m2s[lane] = m2 * m2;
    }
    __syncthreads();
    if (tid == 0) {
        double part = 0.0;
        for (int i = 0; i < 128; i++) part += s_m2s[i];
        g_MK2BP[c * NSEG + s] = part;
    }
}

// ---------------- K7: dist_new -> softmax y_pred; block 75 reduces loss ----------------
__global__ void k_final(float* __restrict__ out) {
    __shared__ double sred[8 * KCLS];
    __shared__ double sdots[KCLS];
    __shared__ double sden2[KCLS], sy2[KCLS];
    int q = blockIdx.x, tid = threadIdx.x;
    int w = tid >> 5, l = tid & 31;

    if (q == NQRY) {
        if (tid == 0) {
            double ssum = 0.0;
            for (int i = 0; i < NQRY; i++) ssum += g_NLL[i];
            out[NQRY * KCLS] = (float)(ssum / (double)NQRY);
        }
        return;
    }

    if (tid < KCLS) {
        double mk2b = 0.0;
        for (int s = 0; s < NSEG; s++) mk2b += g_MK2BP[tid * NSEG + s];
        double den2 = 1.0 + sqrt(fmax(1.0 - 0.01 * mk2b, 0.0));
        sden2[tid] = den2;
        sy2[tid]   = mk2b / (den2 * den2);
    }

    int row = 25 + q;
    double p5[KCLS] = {0.0, 0.0, 0.0, 0.0, 0.0};
    #pragma unroll
    for (int i = 0; i < 4; i++) {
        int d = tid + i * 256;
        double xv = g_P[(size_t)row * DD + d];
        #pragma unroll
        for (int j = 0; j < KCLS; j++) p5[j] += xv * g_M2[(size_t)j * DD + d];
    }
    #pragma unroll
    for (int j = 0; j < KCLS; j++) {
        double v = p5[j];
        #pragma unroll
        for (int o = 16; o > 0; o >>= 1) v += __shfl_down_sync(0xffffffffu, v, o);
        if (l == 0) sred[w * KCLS + j] = v;
    }
    __syncthreads();
    if (tid < KCLS) {
        double r = 0.0;
        #pragma unroll
        for (int ww = 0; ww < 8; ww++) r += sred[ww * KCLS + tid];
        sdots[tid] = r;
    }
    __syncthreads();

    if (tid == 0) {
        double x2 = g_X2[row];
        double dist[KCLS];
        double m = -1e300;
        #pragma unroll
        for (int j = 0; j < KCLS; j++) {
            dist[j] = hdist(x2, sy2[j], sdots[j] / sden2[j]);
            m = fmax(m, -dist[j]);
        }
        double e[KCLS]; double se = 0.0;
        #pragma unroll
        for (int j = 0; j < KCLS; j++) { e[j] = exp(-dist[j] - m); se += e[j]; }
        #pragma unroll
        for (int j = 0; j < KCLS; j++) out[q * KCLS + j] = (float)(e[j] / se);
    }
}

// ---------------- launch ----------------
extern "C" void kernel_launch(void* const* d_in, const int* in_sizes, int n_in,
                              void* d_out, int out_size) {
    const float* feat  = (const float*)d_in[0];
    const int*   label = (const int*)  d_in[1];
    const float* noise = (const float*)d_in[2];
    float* out = (float*)d_out;

    k_transform<<<NROWS, 256>>>(feat);
    k_proto<<<KCLS, 256>>>();
    k_dist1<<<NQRY, 256>>>(label);
    k_stats<<<KCLS * NSEGS, 512>>>(feat);
    k_augrow<<<KCLS * NAUG, 256>>>(noise);
    k_newproto<<<KCLS * NSEG, 512>>>(noise);
    k_final<<<NQRY + 1, 256>>>(out);
}

// round 10
// speedup vs baseline: 3.8006x; 1.4243x over previous
#include <cuda_runtime.h>
#include <math.h>

// Problem constants
#define DD    1024
#define KCLS  5
#define NSUP  5      // support per class
#define NQRY  75     // total queries (K*Q)
#define NAUG  40
#define NROWS 100    // 25 support + 75 queries
#define NSEGS 16     // stats: per-class dim segments (16*64 = 1024)
#define NSEG  8      // newproto: per-class dim segments (8*128 = 1024)
// hyperbolic constants: c = 0.01, sqrt(c) = 0.1

// ---------------- device scratch (static, no runtime alloc) ----------------
__device__ double g_P[NROWS * DD];       // projected Poincare points
__device__ double g_X2[NROWS];           // ||x||^2 per point
__device__ double g_KFAC[NROWS];         // 2/(1 + c||x||^2)
__device__ double g_LAM[NROWS];          // Lorentz factor of Klein point
__device__ double g_PROTO[KCLS * DD];    // initial prototypes
__device__ double g_PX2[KCLS];
__device__ int    g_PRED[NQRY];
__device__ double g_NLL[NQRY];
__device__ double g_MKD[KCLS * DD];      // masked Klein mean per dim
__device__ double g_STD[KCLS * DD];      // per-dim std of masked Euclid pts
__device__ double g_MK2P[KCLS * NSEGS];  // partial sums of mkd^2 (16/class)
__device__ double g_CA[KCLS * NAUG];     // per-aug-row coefficient on s_p
__device__ double g_CB[KCLS * NAUG];     // per-aug-row coefficient on noise
__device__ double g_WL2[KCLS * NAUG];    // per-aug-row Lorentz weight
__device__ double g_M2[KCLS * DD];       // unnormalized refined Klein mean
__device__ double g_MK2BP[KCLS * NSEG];  // partial sums of m2^2 (8/class)

// ---------------- helpers ----------------
__device__ __forceinline__ double blk_reduce(double v, double* sbuf, int nwarps) {
    #pragma unroll
    for (int o = 16; o > 0; o >>= 1) v += __shfl_down_sync(0xffffffffu, v, o);
    int w = threadIdx.x >> 5, l = threadIdx.x & 31;
    if (l == 0) sbuf[w] = v;
    __syncthreads();
    if (w == 0) {
        double r = (l < nwarps) ? sbuf[l] : 0.0;
        #pragma unroll
        for (int o = 16; o > 0; o >>= 1) r += __shfl_down_sync(0xffffffffu, r, o);
        if (l == 0) sbuf[0] = r;
    }
    __syncthreads();
    double r = sbuf[0];
    __syncthreads();
    return r;
}

// Poincare distance given ||x||^2, ||y||^2, <x,y>  (c = 0.01)
__device__ __forceinline__ double hdist(double x2, double y2, double xy) {
    double a    = 1.0 - 0.02 * xy + 0.01 * y2;
    double b    = 1.0 - 0.01 * x2;
    double num2 = a * a * x2 + b * b * y2 - 2.0 * a * b * xy;
    double den  = fmax(1.0 - 0.02 * xy + 1e-4 * x2 * y2, 1e-5);
    double nrm  = sqrt(fmax(num2, 0.0)) / den;
    double z    = fmin(fmax(0.1 * nrm, -1.0 + 1e-5), 1.0 - 1e-5);
    return 20.0 * atanh(z);
}

// ---------------- K1: expmap0 + project + Klein scalars (100 rows) ----------------
__global__ void k_transform(const float* __restrict__ feat) {
    __shared__ double sbuf[8];
    int row = blockIdx.x, tid = threadIdx.x;
    const float* u = feat + (size_t)row * DD;
    double uv[4];
    double s2 = 0.0;
    #pragma unroll
    for (int i = 0; i < 4; i++) { uv[i] = (double)u[tid + i * 256]; s2 += uv[i] * uv[i]; }
    s2 = blk_reduce(s2, sbuf, 8);

    double nrmu = sqrt(s2);
    double un   = fmax(nrmu, 1e-5);
    double s1   = tanh(0.1 * un) / (0.1 * un);
    double e0n  = s1 * nrmu;
    double nrm  = fmax(e0n, 1e-5);
    double s    = s1;
    if (nrm > 9.99) s = s1 * (9.99 / nrm);
    double x2 = s * s * s2;

    #pragma unroll
    for (int i = 0; i < 4; i++)
        g_P[(size_t)row * DD + tid + i * 256] = s * uv[i];

    if (tid == 0) {
        g_X2[row] = x2;
        double kf = 2.0 / (1.0 + 0.01 * x2);
        double k2 = kf * kf * x2;
        g_KFAC[row] = kf;
        g_LAM[row]  = 1.0 / sqrt(fmax(1.0 - 0.01 * k2, 1e-5));
    }
}

// ---------------- K2: initial prototypes (5 classes) ----------------
__global__ void k_proto() {
    __shared__ double sco[NSUP];
    __shared__ double srw;
    __shared__ double sbuf[8];
    int c = blockIdx.x, tid = threadIdx.x;
    if (tid < NSUP) sco[tid] = g_LAM[c * NSUP + tid] * g_KFAC[c * NSUP + tid];
    if (tid == 0) {
        double w = 0.0;
        for (int n = 0; n < NSUP; n++) w += g_LAM[c * NSUP + n];
        srw = 1.0 / w;
    }
    __syncthreads();
    double rwsum = srw;

    double mk[4]; double part = 0.0;
    #pragma unroll
    for (int i = 0; i < 4; i++) {
        int d = tid + i * 256;
        double a = 0.0;
        #pragma unroll
        for (int n = 0; n < NSUP; n++) a += sco[n] * g_P[(size_t)(c * NSUP + n) * DD + d];
        mk[i] = a * rwsum;
        part += mk[i] * mk[i];
    }
    double mk2 = blk_reduce(part, sbuf, 8);
    double den = 1.0 + sqrt(fmax(1.0 - 0.01 * mk2, 0.0));   // k2p
    double rden = 1.0 / den;
    #pragma unroll
    for (int i = 0; i < 4; i++)
        g_PROTO[(size_t)c * DD + tid + i * 256] = mk[i] * rden;
    if (tid == 0) g_PX2[c] = mk2 / (den * den);
}

// ---------------- K3: dist matrix, argmax pred, per-query NLL (75 queries) ----------------
// hdist (fp64 atanh ~long software chain) and exp computed on 5 threads in parallel.
__global__ void k_dist1(const int* __restrict__ label) {
    __shared__ double sred[8 * KCLS];
    __shared__ double sdots[KCLS];
    __shared__ double sdist[KCLS];
    __shared__ double s_max;
    __shared__ double s_e[KCLS];
    int q = blockIdx.x, tid = threadIdx.x;
    int row = 25 + q;
    int w = tid >> 5, l = tid & 31;

    double p5[KCLS] = {0.0, 0.0, 0.0, 0.0, 0.0};
    #pragma unroll
    for (int i = 0; i < 4; i++) {
        int d = tid + i * 256;
        double xv = g_P[(size_t)row * DD + d];
        #pragma unroll
        for (int j = 0; j < KCLS; j++) p5[j] += xv * g_PROTO[(size_t)j * DD + d];
    }
    #pragma unroll
    for (int j = 0; j < KCLS; j++) {
        double v = p5[j];
        #pragma unroll
        for (int o = 16; o > 0; o >>= 1) v += __shfl_down_sync(0xffffffffu, v, o);
        if (l == 0) sred[w * KCLS + j] = v;
    }
    __syncthreads();
    if (tid < KCLS) {
        double r = 0.0;
        #pragma unroll
        for (int ww = 0; ww < 8; ww++) r += sred[ww * KCLS + tid];
        sdots[tid] = r;
    }
    __syncthreads();

    // parallel hdist (one class per thread)
    if (tid < KCLS)
        sdist[tid] = hdist(g_X2[row], g_PX2[tid], sdots[tid]);
    __syncthreads();

    if (tid == 0) {
        int best = 0; double bd = 1e300;
        double m = -1e300;
        #pragma unroll
        for (int j = 0; j < KCLS; j++) {
            if (sdist[j] < bd) { bd = sdist[j]; best = j; }
            m = fmax(m, -sdist[j]);
        }
        g_PRED[q] = best;
        s_max = m;
    }
    __syncthreads();

    // parallel exp
    if (tid < KCLS) s_e[tid] = exp(-sdist[tid] - s_max);
    __syncthreads();

    if (tid == 0) {
        double se = 0.0;
        #pragma unroll
        for (int j = 0; j < KCLS; j++) se += s_e[j];
        double lse = s_max + log(se);
        int lbl = label[NQRY + q];
        g_NLL[q] = lse + sdist[lbl];   // log_softmax(log_softmax(x)) == log_softmax(x)
    }
}

// ---------------- K4: per-class per-dim masked Klein mean + Euclid std ----------------
// grid = KCLS * NSEGS = 80 blocks, 512 threads = 8 point-groups x 64 dims.
// Compaction done with warp ballots (order-preserving), not a serial tid0 loop.
__global__ void __launch_bounds__(512) k_stats(const float* __restrict__ feat) {
    __shared__ double scoef[80];
    __shared__ int    srow[80];
    __shared__ int    swcnt[3];
    __shared__ double swsum[3];
    __shared__ double s_ak[8][64], s_ae[8][64], s_ae2[8][64];
    __shared__ double s_m2[64];
    __shared__ double s_rw, s_cnt;
    __shared__ int    s_m;

    int c = blockIdx.x >> 4, s = blockIdx.x & 15;
    int tid  = threadIdx.x;
    int g    = tid >> 6;          // point-group 0..7
    int lane = tid & 63;          // dim within segment
    int d    = s * 64 + lane;

    // ---- order-preserving ballot compaction over 80 candidate rows ----
    bool active = false;
    int  row_r  = 0;
    double coef_r = 0.0, lm_r = 0.0;
    int  lanepos = 0;
    if (tid < 96) {                                  // warps 0..2 (full warps)
        if (tid < 80) {
            if (tid < NSUP) { row_r = c * NSUP + tid; active = true; }
            else            { row_r = 25 + (tid - NSUP); active = (g_PRED[tid - NSUP] == c); }
            lm_r   = g_LAM[row_r];
            coef_r = lm_r * g_KFAC[row_r];
        }
        unsigned bal = __ballot_sync(0xffffffffu, active);
        lanepos = __popc(bal & ((1u << (tid & 31)) - 1u));
        double wv = active ? lm_r : 0.0;
        #pragma unroll
        for (int o = 16; o > 0; o >>= 1) wv += __shfl_down_sync(0xffffffffu, wv, o);
        if ((tid & 31) == 0) { swcnt[tid >> 5] = __popc(bal); swsum[tid >> 5] = wv; }
    }
    __syncthreads();
    if (tid == 0) {
        int m = swcnt[0] + swcnt[1] + swcnt[2];
        double wsum = swsum[0] + swsum[1] + swsum[2];
        s_rw = 1.0 / wsum; s_cnt = (double)m; s_m = m;
    }
    if (tid < 96 && active) {
        int base = (tid >= 32 ? swcnt[0] : 0) + (tid >= 64 ? swcnt[1] : 0);
        srow[base + lanepos]  = row_r;
        scoef[base + lanepos] = coef_r;
    }
    __syncthreads();
    int m = s_m;

    double ak = 0.0, ae = 0.0, ae2 = 0.0;
    #pragma unroll 4
    for (int ji = g; ji < m; ji += 8) {
        int row   = srow[ji];
        double Pv = g_P[(size_t)row * DD + d];
        double Ev = (double)feat[(size_t)row * DD + d];
        ak  = fma(scoef[ji], Pv, ak);
        ae  += Ev;
        ae2 = fma(Ev, Ev, ae2);
    }
    s_ak[g][lane] = ak; s_ae[g][lane] = ae; s_ae2[g][lane] = ae2;
    __syncthreads();

    if (g == 0) {
        double AK = 0.0, AE = 0.0, AE2 = 0.0;
        #pragma unroll
        for (int gg = 0; gg < 8; gg++) {
            AK += s_ak[gg][lane]; AE += s_ae[gg][lane]; AE2 += s_ae2[gg][lane];
        }
        double cnt = s_cnt;
        double mkd = AK * s_rw;
        g_MKD[(size_t)c * DD + d] = mkd;
        double var = fmax(AE2 - AE * AE / cnt, 0.0) / (cnt - 1.0);
        g_STD[(size_t)c * DD + d] = sqrt(var);
        s_m2[lane] = mkd * mkd;
    }
    __syncthreads();
    if (tid == 0) {
        double part = 0.0;
        for (int i = 0; i < 64; i++) part += s_m2[i];
        g_MK2P[c * NSEGS + s] = part;
    }
}

// ---------------- K5: per (class, aug-row): pt reductions + scalar chain ----------------
// grid = KCLS * NAUG = 200 blocks, 256 threads. Scalars hoisted out of the per-dim loop.
__global__ void k_augrow(const float* __restrict__ noise) {
    __shared__ double sred[8 * 2];
    __shared__ double s_rden, s_x2sp, s_ptfac;

    int c = blockIdx.x / NAUG, j = blockIdx.x % NAUG;
    int tid = threadIdx.x;
    int w = tid >> 5, l = tid & 31;

    if (tid == 0) {
        double mk2 = 0.0;
        for (int s = 0; s < NSEGS; s++) mk2 += g_MK2P[c * NSEGS + s];
        double den = 1.0 + sqrt(fmax(1.0 - 0.01 * mk2, 0.0));
        s_rden  = 1.0 / den;
        double x2sp = mk2 / (den * den);
        s_x2sp  = x2sp;
        s_ptfac = 1.0 - 0.01 * x2sp;
    }
    __syncthreads();
    double rden = s_rden, x2sp = s_x2sp, ptfac = s_ptfac;

    const float* nz = noise + ((size_t)(c * NAUG + j)) * DD;
    double a2 = 0.0, ad = 0.0;
    #pragma unroll
    for (int i = 0; i < 4; i++) {
        int dd = tid + i * 256;
        double wv = (double)nz[dd] * g_STD[(size_t)c * DD + dd];
        a2 = fma(wv, wv, a2);
        ad = fma(g_MKD[(size_t)c * DD + dd], wv, ad);
    }
    #pragma unroll
    for (int o = 16; o > 0; o >>= 1) {
        a2 += __shfl_down_sync(0xffffffffu, a2, o);
        ad += __shfl_down_sync(0xffffffffu, ad, o);
    }
    if (l == 0) { sred[w * 2] = a2; sred[w * 2 + 1] = ad; }
    __syncthreads();

    if (tid == 0) {
        double A2 = 0.0, AD = 0.0;
        #pragma unroll
        for (int ww = 0; ww < 8; ww++) { A2 += sred[ww * 2]; AD += sred[ww * 2 + 1]; }
        double pt2 = ptfac * ptfac * A2;
        double dxp = ptfac * rden * AD;

        double lamx = 2.0 / fmax(1.0 - 0.01 * x2sp, 1e-5);
        double un  = fmax(sqrt(pt2), 1e-5);
        double t   = tanh(0.05 * lamx * un) / (0.1 * un);
        double y2  = t * t * pt2;
        double xy  = t * dxp;
        double A   = 1.0 + 0.02 * xy + 0.01 * y2;
        double B   = ptfac * t;
        double dn  = fmax(1.0 + 0.02 * xy + 1e-4 * x2sp * y2, 1e-5);
        double ex2 = (A * A * x2sp + B * B * pt2 + 2.0 * A * B * dxp) / (dn * dn);
        double kf  = 2.0 / (1.0 + 0.01 * ex2);
        double k2  = kf * kf * ex2;
        double lm  = 1.0 / sqrt(fmax(1.0 - 0.01 * k2, 1e-5));
        g_CA[c * NAUG + j]  = lm * kf * A / dn;
        g_CB[c * NAUG + j]  = lm * kf * B / dn;
        g_WL2[c * NAUG + j] = lm;
    }
}

// ---------------- K6: refined prototype per dim (unnormalized Klein mean) ----------------
// grid = KCLS * NSEG = 40 blocks, 512 threads = 4 row-groups x 128 dims.
__global__ void __launch_bounds__(512) k_newproto(const float* __restrict__ noise) {
    __shared__ double scb[NAUG], sco[NSUP];
    __shared__ double s_accN[4][128];
    __shared__ double s_m2s[128];
    __shared__ double s_rwsum2, s_SA, s_ptfac, s_rden;

    int c = blockIdx.x >> 3, s = blockIdx.x & 7;
    int tid  = threadIdx.x;
    int g    = tid >> 7;
    int lane = tid & 127;
    int d    = s * 128 + lane;

    if (tid < NAUG) scb[tid] = g_CB[c * NAUG + tid];
    if (tid >= 64 && tid < 64 + NSUP) sco[tid - 64] = g_LAM[c * NSUP + tid - 64] * g_KFAC[c * NSUP + tid - 64];
    if (tid == 0) {
        double mk2 = 0.0;
        for (int t = 0; t < NSEGS; t++) mk2 += g_MK2P[c * NSEGS + t];
        double den = 1.0 + sqrt(fmax(1.0 - 0.01 * mk2, 0.0));
        double x2sp = mk2 / (den * den);
        s_rden  = 1.0 / den;
        s_ptfac = 1.0 - 0.01 * x2sp;
        double w2 = 0.0, sa = 0.0;
        for (int n = 0; n < NSUP; n++) w2 += g_LAM[c * NSUP + n];
        for (int j = 0; j < NAUG; j++) { w2 += g_WL2[c * NAUG + j]; sa += g_CA[c * NAUG + j]; }
        s_rwsum2 = 1.0 / w2; s_SA = sa;
    }
    __syncthreads();

    double accN = 0.0;
    #pragma unroll
    for (int ji = 0; ji < 10; ji++) {
        int j = g * 10 + ji;
        accN = fma(scb[j], (double)noise[((size_t)(c * NAUG + j)) * DD + d], accN);
    }
    s_accN[g][lane] = accN;
    __syncthreads();

    if (g == 0) {
        double acc = 0.0;
        #pragma unroll
        for (int n = 0; n < NSUP; n++)
            acc = fma(sco[n], g_P[(size_t)(c * NSUP + n) * DD + d], acc);
        double spd = g_MKD[(size_t)c * DD + d] * s_rden;
        acc += s_SA * spd;
        double AN = s_accN[0][lane] + s_accN[1][lane] + s_accN[2][lane] + s_accN[3][lane];
        acc += AN * s_ptfac * g_STD[(size_t)c * DD + d];

        double m2 = acc * s_rwsum2;
        g_M2[(size_t)c * DD + d] = m2;
        s_m2s[lane] = m2 * m2;
    }
    __syncthreads();
    if (tid == 0) {
        double part = 0.0;
        for (int i = 0; i < 128; i++) part += s_m2s[i];
        g_MK2BP[c * NSEG + s] = part;
    }
}

// ---------------- K7: dist_new -> softmax y_pred; block 75 reduces loss ----------------
// Parallel hdist/exp tails (one class per thread) — cuts the fp64 atanh serial chain 5x.
__global__ void k_final(float* __restrict__ out) {
    __shared__ double sred[8 * KCLS];
    __shared__ double sdots[KCLS];
    __shared__ double sden2[KCLS], sy2[KCLS];
    __shared__ double sdist[KCLS];
    __shared__ double s_max, s_sum;
    __shared__ double s_e[KCLS];
    int q = blockIdx.x, tid = threadIdx.x;
    int w = tid >> 5, l = tid & 31;

    if (q == NQRY) {
        if (tid == 0) {
            double ssum = 0.0;
            for (int i = 0; i < NQRY; i++) ssum += g_NLL[i];
            out[NQRY * KCLS] = (float)(ssum / (double)NQRY);
        }
        return;
    }

    if (tid < KCLS) {
        double mk2b = 0.0;
        for (int s = 0; s < NSEG; s++) mk2b += g_MK2BP[tid * NSEG + s];
        double den2 = 1.0 + sqrt(fmax(1.0 - 0.01 * mk2b, 0.0));
        sden2[tid] = den2;
        sy2[tid]   = mk2b / (den2 * den2);
    }

    int row = 25 + q;
    double p5[KCLS] = {0.0, 0.0, 0.0, 0.0, 0.0};
    #pragma unroll
    for (int i = 0; i < 4; i++) {
        int d = tid + i * 256;
        double xv = g_P[(size_t)row * DD + d];
        #pragma unroll
        for (int j = 0; j < KCLS; j++) p5[j] += xv * g_M2[(size_t)j * DD + d];
    }
    #pragma unroll
    for (int j = 0; j < KCLS; j++) {
        double v = p5[j];
        #pragma unroll
        for (int o = 16; o > 0; o >>= 1) v += __shfl_down_sync(0xffffffffu, v, o);
        if (l == 0) sred[w * KCLS + j] = v;
    }
    __syncthreads();
    if (tid < KCLS) {
        double r = 0.0;
        #pragma unroll
        for (int ww = 0; ww < 8; ww++) r += sred[ww * KCLS + tid];
        sdots[tid] = r;
    }
    __syncthreads();

    // parallel hdist (one class per thread)
    if (tid < KCLS)
        sdist[tid] = hdist(g_X2[row], sy2[tid], sdots[tid] / sden2[tid]);
    __syncthreads();

    if (tid == 0) {
        double m = -1e300;
        #pragma unroll
        for (int j = 0; j < KCLS; j++) m = fmax(m, -sdist[j]);
        s_max = m;
    }
    __syncthreads();

    // parallel exp
    if (tid < KCLS) s_e[tid] = exp(-sdist[tid] - s_max);
    __syncthreads();

    if (tid == 0) {
        double se = 0.0;
        #pragma unroll
        for (int j = 0; j < KCLS; j++) se += s_e[j];
        s_sum = se;
    }
    __syncthreads();

    if (tid < KCLS) out[q * KCLS + tid] = (float)(s_e[tid] / s_sum);
}

// ---------------- launch ----------------
extern "C" void kernel_launch(void* const* d_in, const int* in_sizes, int n_in,
                              void* d_out, int out_size) {
    const float* feat  = (const float*)d_in[0];
    const int*   label = (const int*)  d_in[1];
    const float* noise = (const float*)d_in[2];
    float* out = (float*)d_out;

    k_transform<<<NROWS, 256>>>(feat);
    k_proto<<<KCLS, 256>>>();
    k_dist1<<<NQRY, 256>>>(label);
    k_stats<<<KCLS * NSEGS, 512>>>(feat);
    k_augrow<<<KCLS * NAUG, 256>>>(noise);
    k_newproto<<<KCLS * NSEG, 512>>>(noise);
    k_final<<<NQRY + 1, 256>>>(out);
}

// round 11
// speedup vs baseline: 3.9067x; 1.0279x over previous
#include <cuda_runtime.h>
#include <math.h>

// Problem constants
#define DD    1024
#define KCLS  5
#define NSUP  5      // support per class
#define NQRY  75     // total queries (K*Q)
#define NAUG  40
#define NROWS 100    // 25 support + 75 queries
#define NSEGS 16     // stats: per-class dim segments (16*64 = 1024)
#define NSEG  8      // newproto: per-class dim segments (8*128 = 1024)
// hyperbolic constants: c = 0.01, sqrt(c) = 0.1

// ---------------- device scratch (static, no runtime alloc) ----------------
__device__ double g_P[NROWS * DD];       // projected Poincare points
__device__ double g_X2[NROWS];           // ||x||^2 per point
__device__ double g_KFAC[NROWS];         // 2/(1 + c||x||^2)
__device__ double g_LAM[NROWS];          // Lorentz factor of Klein point
__device__ double g_PROTO[KCLS * DD];    // initial prototypes
__device__ double g_PX2[KCLS];
__device__ int    g_PRED[NQRY];
__device__ double g_NLL[NQRY];
__device__ double g_MKD[KCLS * DD];      // masked Klein mean per dim
__device__ double g_STD[KCLS * DD];      // per-dim std of masked Euclid pts
__device__ double g_MK2P[KCLS * NSEGS];  // partial sums of mkd^2 (16/class)
__device__ double g_CA[KCLS * NAUG];     // per-aug-row coefficient on s_p
__device__ double g_CB[KCLS * NAUG];     // per-aug-row coefficient on noise
__device__ double g_WL2[KCLS * NAUG];    // per-aug-row Lorentz weight
__device__ double g_M2[KCLS * DD];       // unnormalized refined Klein mean
__device__ double g_MK2BP[KCLS * NSEG];  // partial sums of m2^2 (8/class)

// ---------------- helpers ----------------
__device__ __forceinline__ double blk_reduce(double v, double* sbuf, int nwarps) {
    #pragma unroll
    for (int o = 16; o > 0; o >>= 1) v += __shfl_down_sync(0xffffffffu, v, o);
    int w = threadIdx.x >> 5, l = threadIdx.x & 31;
    if (l == 0) sbuf[w] = v;
    __syncthreads();
    if (w == 0) {
        double r = (l < nwarps) ? sbuf[l] : 0.0;
        #pragma unroll
        for (int o = 16; o > 0; o >>= 1) r += __shfl_down_sync(0xffffffffu, r, o);
        if (l == 0) sbuf[0] = r;
    }
    __syncthreads();
    double r = sbuf[0];
    __syncthreads();
    return r;
}

// Poincare distance given ||x||^2, ||y||^2, <x,y>  (c = 0.01)
__device__ __forceinline__ double hdist(double x2, double y2, double xy) {
    double a    = 1.0 - 0.02 * xy + 0.01 * y2;
    double b    = 1.0 - 0.01 * x2;
    double num2 = a * a * x2 + b * b * y2 - 2.0 * a * b * xy;
    double den  = fmax(1.0 - 0.02 * xy + 1e-4 * x2 * y2, 1e-5);
    double nrm  = sqrt(fmax(num2, 0.0)) / den;
    double z    = fmin(fmax(0.1 * nrm, -1.0 + 1e-5), 1.0 - 1e-5);
    return 20.0 * atanh(z);
}

// ---------------- K1: expmap0 + project + Klein scalars (100 rows) ----------------
__global__ void k_transform(const float* __restrict__ feat) {
    __shared__ double sbuf[8];
    int row = blockIdx.x, tid = threadIdx.x;
    const float* u = feat + (size_t)row * DD;
    double uv[4];
    double s2 = 0.0;
    #pragma unroll
    for (int i = 0; i < 4; i++) { uv[i] = (double)u[tid + i * 256]; s2 += uv[i] * uv[i]; }
    s2 = blk_reduce(s2, sbuf, 8);

    double nrmu = sqrt(s2);
    double un   = fmax(nrmu, 1e-5);
    double s1   = tanh(0.1 * un) / (0.1 * un);
    double e0n  = s1 * nrmu;
    double nrm  = fmax(e0n, 1e-5);
    double s    = s1;
    if (nrm > 9.99) s = s1 * (9.99 / nrm);
    double x2 = s * s * s2;

    #pragma unroll
    for (int i = 0; i < 4; i++)
        g_P[(size_t)row * DD + tid + i * 256] = s * uv[i];

    if (tid == 0) {
        g_X2[row] = x2;
        double kf = 2.0 / (1.0 + 0.01 * x2);
        double k2 = kf * kf * x2;
        g_KFAC[row] = kf;
        g_LAM[row]  = 1.0 / sqrt(fmax(1.0 - 0.01 * k2, 1e-5));
    }
}

// ---------------- K2: initial prototypes (5 classes) ----------------
__global__ void k_proto() {
    __shared__ double sco[NSUP];
    __shared__ double srw;
    __shared__ double sbuf[8];
    int c = blockIdx.x, tid = threadIdx.x;
    if (tid < NSUP) sco[tid] = g_LAM[c * NSUP + tid] * g_KFAC[c * NSUP + tid];
    if (tid == 0) {
        double w = 0.0;
        for (int n = 0; n < NSUP; n++) w += g_LAM[c * NSUP + n];
        srw = 1.0 / w;
    }
    __syncthreads();
    double rwsum = srw;

    double mk[4]; double part = 0.0;
    #pragma unroll
    for (int i = 0; i < 4; i++) {
        int d = tid + i * 256;
        double a = 0.0;
        #pragma unroll
        for (int n = 0; n < NSUP; n++) a += sco[n] * g_P[(size_t)(c * NSUP + n) * DD + d];
        mk[i] = a * rwsum;
        part += mk[i] * mk[i];
    }
    double mk2 = blk_reduce(part, sbuf, 8);
    double den = 1.0 + sqrt(fmax(1.0 - 0.01 * mk2, 0.0));   // k2p
    double rden = 1.0 / den;
    #pragma unroll
    for (int i = 0; i < 4; i++)
        g_PROTO[(size_t)c * DD + tid + i * 256] = mk[i] * rden;
    if (tid == 0) g_PX2[c] = mk2 / (den * den);
}

// ---------------- K3: dist matrix, argmax pred, per-query NLL (75 queries) ----------------
__global__ void k_dist1(const int* __restrict__ label) {
    __shared__ double sred[8 * KCLS];
    __shared__ double sdots[KCLS];
    __shared__ double sdist[KCLS];
    __shared__ double s_max;
    __shared__ double s_e[KCLS];
    int q = blockIdx.x, tid = threadIdx.x;
    int row = 25 + q;
    int w = tid >> 5, l = tid & 31;

    double p5[KCLS] = {0.0, 0.0, 0.0, 0.0, 0.0};
    #pragma unroll
    for (int i = 0; i < 4; i++) {
        int d = tid + i * 256;
        double xv = g_P[(size_t)row * DD + d];
        #pragma unroll
        for (int j = 0; j < KCLS; j++) p5[j] += xv * g_PROTO[(size_t)j * DD + d];
    }
    #pragma unroll
    for (int j = 0; j < KCLS; j++) {
        double v = p5[j];
        #pragma unroll
        for (int o = 16; o > 0; o >>= 1) v += __shfl_down_sync(0xffffffffu, v, o);
        if (l == 0) sred[w * KCLS + j] = v;
    }
    __syncthreads();
    if (tid < KCLS) {
        double r = 0.0;
        #pragma unroll
        for (int ww = 0; ww < 8; ww++) r += sred[ww * KCLS + tid];
        sdots[tid] = r;
    }
    __syncthreads();

    if (tid < KCLS)
        sdist[tid] = hdist(g_X2[row], g_PX2[tid], sdots[tid]);
    __syncthreads();

    if (tid == 0) {
        int best = 0; double bd = 1e300;
        double m = -1e300;
        #pragma unroll
        for (int j = 0; j < KCLS; j++) {
            if (sdist[j] < bd) { bd = sdist[j]; best = j; }
            m = fmax(m, -sdist[j]);
        }
        g_PRED[q] = best;
        s_max = m;
    }
    __syncthreads();

    if (tid < KCLS) s_e[tid] = exp(-sdist[tid] - s_max);
    __syncthreads();

    if (tid == 0) {
        double se = 0.0;
        #pragma unroll
        for (int j = 0; j < KCLS; j++) se += s_e[j];
        double lse = s_max + log(se);
        int lbl = label[NQRY + q];
        g_NLL[q] = lse + sdist[lbl];   // log_softmax(log_softmax(x)) == log_softmax(x)
    }
}

// ---------------- K4: per-class per-dim masked Klein mean + Euclid std ----------------
// grid = KCLS * NSEGS = 80 blocks, 512 threads = 8 point-groups x 64 dims.
// Klein path fp64; Euclid mean/var path fp32 (reference computes it in fp32 too).
__global__ void __launch_bounds__(512) k_stats(const float* __restrict__ feat) {
    __shared__ double scoef[80];
    __shared__ int    srow[80];
    __shared__ int    swcnt[3];
    __shared__ double swsum[3];
    __shared__ double s_ak[8][64];
    __shared__ float  s_ae[8][64], s_ae2[8][64];
    __shared__ double s_m2[64];
    __shared__ double s_rw, s_cnt;
    __shared__ int    s_m;

    int c = blockIdx.x >> 4, s = blockIdx.x & 15;
    int tid  = threadIdx.x;
    int g    = tid >> 6;          // point-group 0..7
    int lane = tid & 63;          // dim within segment
    int d    = s * 64 + lane;

    // ---- order-preserving ballot compaction over 80 candidate rows ----
    bool active = false;
    int  row_r  = 0;
    double coef_r = 0.0, lm_r = 0.0;
    int  lanepos = 0;
    if (tid < 96) {
        if (tid < 80) {
            if (tid < NSUP) { row_r = c * NSUP + tid; active = true; }
            else            { row_r = 25 + (tid - NSUP); active = (g_PRED[tid - NSUP] == c); }
            lm_r   = g_LAM[row_r];
            coef_r = lm_r * g_KFAC[row_r];
        }
        unsigned bal = __ballot_sync(0xffffffffu, active);
        lanepos = __popc(bal & ((1u << (tid & 31)) - 1u));
        double wv = active ? lm_r : 0.0;
        #pragma unroll
        for (int o = 16; o > 0; o >>= 1) wv += __shfl_down_sync(0xffffffffu, wv, o);
        if ((tid & 31) == 0) { swcnt[tid >> 5] = __popc(bal); swsum[tid >> 5] = wv; }
    }
    __syncthreads();
    if (tid == 0) {
        int m = swcnt[0] + swcnt[1] + swcnt[2];
        double wsum = swsum[0] + swsum[1] + swsum[2];
        s_rw = 1.0 / wsum; s_cnt = (double)m; s_m = m;
    }
    if (tid < 96 && active) {
        int base = (tid >= 32 ? swcnt[0] : 0) + (tid >= 64 ? swcnt[1] : 0);
        srow[base + lanepos]  = row_r;
        scoef[base + lanepos] = coef_r;
    }
    __syncthreads();
    int m = s_m;

    double ak = 0.0;
    float  ae = 0.f, ae2 = 0.f;
    #pragma unroll 4
    for (int ji = g; ji < m; ji += 8) {
        int row   = srow[ji];
        double Pv = g_P[(size_t)row * DD + d];
        float  Ev = feat[(size_t)row * DD + d];
        ak  = fma(scoef[ji], Pv, ak);
        ae  += Ev;
        ae2 = fmaf(Ev, Ev, ae2);
    }
    s_ak[g][lane] = ak; s_ae[g][lane] = ae; s_ae2[g][lane] = ae2;
    __syncthreads();

    if (g == 0) {
        double AK = 0.0;
        float  AEf = 0.f, AE2f = 0.f;
        #pragma unroll
        for (int gg = 0; gg < 8; gg++) {
            AK += s_ak[gg][lane]; AEf += s_ae[gg][lane]; AE2f += s_ae2[gg][lane];
        }
        double AE = (double)AEf, AE2 = (double)AE2f;
        double cnt = s_cnt;
        double mkd = AK * s_rw;
        g_MKD[(size_t)c * DD + d] = mkd;
        double var = fmax(AE2 - AE * AE / cnt, 0.0) / (cnt - 1.0);
        g_STD[(size_t)c * DD + d] = sqrt(var);
        s_m2[lane] = mkd * mkd;
    }
    __syncthreads();
    if (tid == 0) {
        double part = 0.0;
        for (int i = 0; i < 64; i++) part += s_m2[i];
        g_MK2P[c * NSEGS + s] = part;
    }
}

// ---------------- K5: per (class, 2 aug-rows): pt reductions + scalar chain ----------------
// grid = 100 blocks (= 1 wave), 512 threads = 2 halves x 256. Half h handles row 2*b+h.
// Rows 2b,2b+1 always share a class (NAUG=40 even), so class scalars computed once.
__global__ void __launch_bounds__(512) k_augrow(const float* __restrict__ noise) {
    __shared__ double sred[16 * 2];
    __shared__ double s_rden, s_x2sp, s_ptfac;

    int tid = threadIdx.x;
    int half = tid >> 8;           // 0 or 1
    int htid = tid & 255;          // thread within half
    int w = tid >> 5, l = tid & 31;
    int r = blockIdx.x * 2 + half; // global aug row 0..199
    int c = r / NAUG;

    if (tid == 0) {
        double mk2 = 0.0;
        for (int s = 0; s < NSEGS; s++) mk2 += g_MK2P[c * NSEGS + s];
        double den = 1.0 + sqrt(fmax(1.0 - 0.01 * mk2, 0.0));
        s_rden  = 1.0 / den;
        double x2sp = mk2 / (den * den);
        s_x2sp  = x2sp;
        s_ptfac = 1.0 - 0.01 * x2sp;
    }
    __syncthreads();
    double rden = s_rden, x2sp = s_x2sp, ptfac = s_ptfac;

    const float* nz = noise + (size_t)r * DD;
    double a2 = 0.0, ad = 0.0;
    #pragma unroll
    for (int i = 0; i < 4; i++) {
        int dd = htid + i * 256;
        double wv = (double)nz[dd] * g_STD[(size_t)c * DD + dd];
        a2 = fma(wv, wv, a2);
        ad = fma(g_MKD[(size_t)c * DD + dd], wv, ad);
    }
    #pragma unroll
    for (int o = 16; o > 0; o >>= 1) {
        a2 += __shfl_down_sync(0xffffffffu, a2, o);
        ad += __shfl_down_sync(0xffffffffu, ad, o);
    }
    if (l == 0) { sred[w * 2] = a2; sred[w * 2 + 1] = ad; }
    __syncthreads();

    if (htid == 0) {  // tid 0 and tid 256: one scalar chain per row
        int wbase = half * 8;
        double A2 = 0.0, AD = 0.0;
        #pragma unroll
        for (int ww = 0; ww < 8; ww++) { A2 += sred[(wbase + ww) * 2]; AD += sred[(wbase + ww) * 2 + 1]; }
        double pt2 = ptfac * ptfac * A2;
        double dxp = ptfac * rden * AD;

        double lamx = 2.0 / fmax(1.0 - 0.01 * x2sp, 1e-5);
        double un  = fmax(sqrt(pt2), 1e-5);
        double t   = tanh(0.05 * lamx * un) / (0.1 * un);
        double y2  = t * t * pt2;
        double xy  = t * dxp;
        double A   = 1.0 + 0.02 * xy + 0.01 * y2;
        double B   = ptfac * t;
        double dn  = fmax(1.0 + 0.02 * xy + 1e-4 * x2sp * y2, 1e-5);
        double idn = 1.0 / dn;
        double ex2 = (A * A * x2sp + B * B * pt2 + 2.0 * A * B * dxp) * (idn * idn);
        double kf  = 2.0 / (1.0 + 0.01 * ex2);
        double k2  = kf * kf * ex2;
        double lm  = 1.0 / sqrt(fmax(1.0 - 0.01 * k2, 1e-5));
        double lkd = lm * kf * idn;
        g_CA[r]  = lkd * A;
        g_CB[r]  = lkd * B;
        g_WL2[r] = lm;
    }
}

// ---------------- K6: refined prototype per dim (unnormalized Klein mean) ----------------
// grid = KCLS * NSEG = 40 blocks, 512 threads = 4 row-groups x 128 dims.
__global__ void __launch_bounds__(512) k_newproto(const float* __restrict__ noise) {
    __shared__ double scb[NAUG], sco[NSUP];
    __shared__ double s_accN[4][128];
    __shared__ double s_m2s[128];
    __shared__ double s_rwsum2, s_SA, s_ptfac, s_rden;

    int c = blockIdx.x >> 3, s = blockIdx.x & 7;
    int tid  = threadIdx.x;
    int g    = tid >> 7;
    int lane = tid & 127;
    int d    = s * 128 + lane;

    if (tid < NAUG) scb[tid] = g_CB[c * NAUG + tid];
    if (tid >= 64 && tid < 64 + NSUP) sco[tid - 64] = g_LAM[c * NSUP + tid - 64] * g_KFAC[c * NSUP + tid - 64];
    if (tid == 0) {
        double mk2 = 0.0;
        for (int t = 0; t < NSEGS; t++) mk2 += g_MK2P[c * NSEGS + t];
        double den = 1.0 + sqrt(fmax(1.0 - 0.01 * mk2, 0.0));
        double x2sp = mk2 / (den * den);
        s_rden  = 1.0 / den;
        s_ptfac = 1.0 - 0.01 * x2sp;
        double w2 = 0.0, sa = 0.0;
        for (int n = 0; n < NSUP; n++) w2 += g_LAM[c * NSUP + n];
        for (int j = 0; j < NAUG; j++) { w2 += g_WL2[c * NAUG + j]; sa += g_CA[c * NAUG + j]; }
        s_rwsum2 = 1.0 / w2; s_SA = sa;
    }
    __syncthreads();

    double accN = 0.0;
    #pragma unroll
    for (int ji = 0; ji < 10; ji++) {
        int j = g * 10 + ji;
        accN = fma(scb[j], (double)noise[((size_t)(c * NAUG + j)) * DD + d], accN);
    }
    s_accN[g][lane] = accN;
    __syncthreads();

    if (g == 0) {
        double acc = 0.0;
        #pragma unroll
        for (int n = 0; n < NSUP; n++)
            acc = fma(sco[n], g_P[(size_t)(c * NSUP + n) * DD + d], acc);
        double spd = g_MKD[(size_t)c * DD + d] * s_rden;
        acc += s_SA * spd;
        double AN = s_accN[0][lane] + s_accN[1][lane] + s_accN[2][lane] + s_accN[3][lane];
        acc += AN * s_ptfac * g_STD[(size_t)c * DD + d];

        double m2 = acc * s_rwsum2;
        g_M2[(size_t)c * DD + d] = m2;
        s_m2s[lane] = m2 * m2;
    }
    __syncthreads();
    if (tid == 0) {
        double part = 0.0;
        for (int i = 0; i < 128; i++) part += s_m2s[i];
        g_MK2BP[c * NSEG + s] = part;
    }
}

// ---------------- K7: dist_new -> softmax y_pred; block 75 reduces loss ----------------
__global__ void k_final(float* __restrict__ out) {
    __shared__ double sred[8 * KCLS];
    __shared__ double sdots[KCLS];
    __shared__ double sden2[KCLS], sy2[KCLS];
    __shared__ double sdist[KCLS];
    __shared__ double s_max, s_sum;
    __shared__ double s_e[KCLS];
    int q = blockIdx.x, tid = threadIdx.x;
    int w = tid >> 5, l = tid & 31;

    if (q == NQRY) {
        if (tid == 0) {
            double ssum = 0.0;
            for (int i = 0; i < NQRY; i++) ssum += g_NLL[i];
            out[NQRY * KCLS] = (float)(ssum / (double)NQRY);
        }
        return;
    }

    if (tid < KCLS) {
        double mk2b = 0.0;
        for (int s = 0; s < NSEG; s++) mk2b += g_MK2BP[tid * NSEG + s];
        double den2 = 1.0 + sqrt(fmax(1.0 - 0.01 * mk2b, 0.0));
        sden2[tid] = den2;
        sy2[tid]   = mk2b / (den2 * den2);
    }

    int row = 25 + q;
    double p5[KCLS] = {0.0, 0.0, 0.0, 0.0, 0.0};
    #pragma unroll
    for (int i = 0; i < 4; i++) {
        int d = tid + i * 256;
        double xv = g_P[(size_t)row * DD + d];
        #pragma unroll
        for (int j = 0; j < KCLS; j++) p5[j] += xv * g_M2[(size_t)j * DD + d];
    }
    #pragma unroll
    for (int j = 0; j < KCLS; j++) {
        double v = p5[j];
        #pragma unroll
        for (int o = 16; o > 0; o >>= 1) v += __shfl_down_sync(0xffffffffu, v, o);
        if (l == 0) sred[w * KCLS + j] = v;
    }
    __syncthreads();
    if (tid < KCLS) {
        double r = 0.0;
        #pragma unroll
        for (int ww = 0; ww < 8; ww++) r += sred[ww * KCLS + tid];
        sdots[tid] = r;
    }
    __syncthreads();

    if (tid < KCLS)
        sdist[tid] = hdist(g_X2[row], sy2[tid], sdots[tid] / sden2[tid]);
    __syncthreads();

    if (tid == 0) {
        double m = -1e300;
        #pragma unroll
        for (int j = 0; j < KCLS; j++) m = fmax(m, -sdist[j]);
        s_max = m;
    }
    __syncthreads();

    if (tid < KCLS) s_e[tid] = exp(-sdist[tid] - s_max);
    __syncthreads();

    if (tid == 0) {
        double se = 0.0;
        #pragma unroll
        for (int j = 0; j < KCLS; j++) se += s_e[j];
        s_sum = se;
    }
    __syncthreads();

    if (tid < KCLS) out[q * KCLS + tid] = (float)(s_e[tid] / s_sum);
}

// ---------------- launch ----------------
extern "C" void kernel_launch(void* const* d_in, const int* in_sizes, int n_in,
                              void* d_out, int out_size) {
    const float* feat  = (const float*)d_in[0];
    const int*   label = (const int*)  d_in[1];
    const float* noise = (const float*)d_in[2];
    float* out = (float*)d_out;

    k_transform<<<NROWS, 256>>>(feat);
    k_proto<<<KCLS, 256>>>();
    k_dist1<<<NQRY, 256>>>(label);
    k_stats<<<KCLS * NSEGS, 512>>>(feat);
    k_augrow<<<100, 512>>>(noise);
    k_newproto<<<KCLS * NSEG, 512>>>(noise);
    k_final<<<NQRY + 1, 256>>>(out);
}

// round 12
// speedup vs baseline: 4.5094x; 1.1543x over previous
#include <cuda_runtime.h>
#include <math.h>

// Problem constants
#define DD    1024
#define KCLS  5
#define NSUP  5      // support per class
#define NQRY  75     // total queries (K*Q)
#define NAUG  40
#define NROWS 100    // 25 support + 75 queries
#define NSEGS 16     // stats: per-class dim segments (16*64 = 1024)
#define NSEG  8      // newproto: per-class dim segments (8*128 = 1024)
// hyperbolic constants: c = 0.01, sqrt(c) = 0.1

// ---------------- device scratch (static, no runtime alloc) ----------------
__device__ double g_P[NROWS * DD];       // projected Poincare points
__device__ double g_X2[NROWS];           // ||x||^2 per point
__device__ double g_KFAC[NROWS];         // 2/(1 + c||x||^2)
__device__ double g_LAM[NROWS];          // Lorentz factor of Klein point
__device__ double g_PROTO[KCLS * DD];    // initial prototypes
__device__ double g_PX2[KCLS];
__device__ int    g_PRED[NQRY];
__device__ double g_NLL[NQRY];
__device__ double g_MKD[KCLS * DD];      // masked Klein mean per dim
__device__ double g_STD[KCLS * DD];      // per-dim std of masked Euclid pts
__device__ double g_MK2P[KCLS * NSEGS];  // partial sums of mkd^2 (16/class)
__device__ double g_CA[KCLS * NAUG];     // per-aug-row coefficient on s_p
__device__ double g_CB[KCLS * NAUG];     // per-aug-row coefficient on noise
__device__ double g_WL2[KCLS * NAUG];    // per-aug-row Lorentz weight
__device__ double g_M2[KCLS * DD];       // unnormalized refined Klein mean
__device__ double g_MK2BP[KCLS * NSEG];  // partial sums of m2^2 (8/class)

// ---------------- helpers ----------------
__device__ __forceinline__ double blk_reduce(double v, double* sbuf, int nwarps) {
    #pragma unroll
    for (int o = 16; o > 0; o >>= 1) v += __shfl_down_sync(0xffffffffu, v, o);
    int w = threadIdx.x >> 5, l = threadIdx.x & 31;
    if (l == 0) sbuf[w] = v;
    __syncthreads();
    if (w == 0) {
        double r = (l < nwarps) ? sbuf[l] : 0.0;
        #pragma unroll
        for (int o = 16; o > 0; o >>= 1) r += __shfl_down_sync(0xffffffffu, r, o);
        if (l == 0) sbuf[0] = r;
    }
    __syncthreads();
    double r = sbuf[0];
    __syncthreads();
    return r;
}

// pairwise tree sums (break 47-cyc fp64 dependency chains)
__device__ __forceinline__ double sum8(const double* a, int stride) {
    double t0 = a[0] + a[stride], t1 = a[2*stride] + a[3*stride];
    double t2 = a[4*stride] + a[5*stride], t3 = a[6*stride] + a[7*stride];
    return (t0 + t1) + (t2 + t3);
}
__device__ __forceinline__ double sum16(const double* a) {
    double t0 = a[0]+a[1],   t1 = a[2]+a[3],   t2 = a[4]+a[5],   t3 = a[6]+a[7];
    double t4 = a[8]+a[9],   t5 = a[10]+a[11], t6 = a[12]+a[13], t7 = a[14]+a[15];
    return ((t0+t1)+(t2+t3)) + ((t4+t5)+(t6+t7));
}

// Poincare distance given ||x||^2, ||y||^2, <x,y>  (c = 0.01)
__device__ __forceinline__ double hdist(double x2, double y2, double xy) {
    double a    = 1.0 - 0.02 * xy + 0.01 * y2;
    double b    = 1.0 - 0.01 * x2;
    double num2 = a * a * x2 + b * b * y2 - 2.0 * a * b * xy;
    double den  = fmax(1.0 - 0.02 * xy + 1e-4 * x2 * y2, 1e-5);
    double nrm  = sqrt(fmax(num2, 0.0)) / den;
    double z    = fmin(fmax(0.1 * nrm, -1.0 + 1e-5), 1.0 - 1e-5);
    return 20.0 * atanh(z);
}

// ---------------- K1: expmap0 + project + Klein scalars (100 rows) ----------------
__global__ void k_transform(const float* __restrict__ feat) {
    __shared__ double sbuf[8];
    int row = blockIdx.x, tid = threadIdx.x;
    const float* u = feat + (size_t)row * DD;
    double uv[4];
    double s2 = 0.0;
    #pragma unroll
    for (int i = 0; i < 4; i++) { uv[i] = (double)u[tid + i * 256]; s2 += uv[i] * uv[i]; }
    s2 = blk_reduce(s2, sbuf, 8);

    double nrmu = sqrt(s2);
    double un   = fmax(nrmu, 1e-5);
    double s1   = tanh(0.1 * un) / (0.1 * un);
    double e0n  = s1 * nrmu;
    double nrm  = fmax(e0n, 1e-5);
    double s    = s1;
    if (nrm > 9.99) s = s1 * (9.99 / nrm);
    double x2 = s * s * s2;

    #pragma unroll
    for (int i = 0; i < 4; i++)
        g_P[(size_t)row * DD + tid + i * 256] = s * uv[i];

    if (tid == 0) {
        g_X2[row] = x2;
        double kf = 2.0 / (1.0 + 0.01 * x2);
        double k2 = kf * kf * x2;
        g_KFAC[row] = kf;
        g_LAM[row]  = 1.0 / sqrt(fmax(1.0 - 0.01 * k2, 1e-5));
    }
}

// ---------------- K2: initial prototypes (5 classes) ----------------
__global__ void k_proto() {
    __shared__ double sco[NSUP];
    __shared__ double srw;
    __shared__ double sbuf[8];
    int c = blockIdx.x, tid = threadIdx.x;
    if (tid < NSUP) sco[tid] = g_LAM[c * NSUP + tid] * g_KFAC[c * NSUP + tid];
    if (tid == 0) {
        double w01 = g_LAM[c*NSUP] + g_LAM[c*NSUP+1];
        double w23 = g_LAM[c*NSUP+2] + g_LAM[c*NSUP+3];
        srw = 1.0 / ((w01 + w23) + g_LAM[c*NSUP+4]);
    }
    __syncthreads();
    double rwsum = srw;

    double mk[4]; double part = 0.0;
    #pragma unroll
    for (int i = 0; i < 4; i++) {
        int d = tid + i * 256;
        double a = 0.0;
        #pragma unroll
        for (int n = 0; n < NSUP; n++) a += sco[n] * g_P[(size_t)(c * NSUP + n) * DD + d];
        mk[i] = a * rwsum;
        part += mk[i] * mk[i];
    }
    double mk2 = blk_reduce(part, sbuf, 8);
    double den = 1.0 + sqrt(fmax(1.0 - 0.01 * mk2, 0.0));   // k2p
    double rden = 1.0 / den;
    #pragma unroll
    for (int i = 0; i < 4; i++)
        g_PROTO[(size_t)c * DD + tid + i * 256] = mk[i] * rden;
    if (tid == 0) g_PX2[c] = mk2 / (den * den);
}

// ---------------- K3: dist matrix, argmax pred, per-query NLL (75 queries) ----------------
__global__ void k_dist1(const int* __restrict__ label) {
    __shared__ double sred[8 * KCLS];
    __shared__ double sdots[KCLS];
    __shared__ double sdist[KCLS];
    __shared__ double s_max;
    __shared__ double s_e[KCLS];
    int q = blockIdx.x, tid = threadIdx.x;
    int row = 25 + q;
    int w = tid >> 5, l = tid & 31;

    double p5[KCLS] = {0.0, 0.0, 0.0, 0.0, 0.0};
    #pragma unroll
    for (int i = 0; i < 4; i++) {
        int d = tid + i * 256;
        double xv = g_P[(size_t)row * DD + d];
        #pragma unroll
        for (int j = 0; j < KCLS; j++) p5[j] += xv * g_PROTO[(size_t)j * DD + d];
    }
    #pragma unroll
    for (int j = 0; j < KCLS; j++) {
        double v = p5[j];
        #pragma unroll
        for (int o = 16; o > 0; o >>= 1) v += __shfl_down_sync(0xffffffffu, v, o);
        if (l == 0) sred[w * KCLS + j] = v;
    }
    __syncthreads();
    if (tid < KCLS) sdots[tid] = sum8(&sred[tid], KCLS);   // pairwise over 8 warps
    __syncthreads();

    if (tid < KCLS)
        sdist[tid] = hdist(g_X2[row], g_PX2[tid], sdots[tid]);
    __syncthreads();

    if (tid == 0) {
        int best = 0; double bd = 1e300;
        double m = -1e300;
        #pragma unroll
        for (int j = 0; j < KCLS; j++) {
            if (sdist[j] < bd) { bd = sdist[j]; best = j; }
            m = fmax(m, -sdist[j]);
        }
        g_PRED[q] = best;
        s_max = m;
    }
    __syncthreads();

    if (tid < KCLS) s_e[tid] = exp(-sdist[tid] - s_max);
    __syncthreads();

    if (tid == 0) {
        double se = ((s_e[0] + s_e[1]) + (s_e[2] + s_e[3])) + s_e[4];
        double lse = s_max + log(se);
        int lbl = label[NQRY + q];
        g_NLL[q] = lse + sdist[lbl];   // log_softmax(log_softmax(x)) == log_softmax(x)
    }
}

// ---------------- K4: per-class per-dim masked Klein mean + Euclid std ----------------
// grid = KCLS * NSEGS = 80 blocks, 512 threads = 8 point-groups x 64 dims.
// All fp64 reductions are trees; no serial 47-cyc add chains.
__global__ void __launch_bounds__(512) k_stats(const float* __restrict__ feat) {
    __shared__ double scoef[80];
    __shared__ int    srow[80];
    __shared__ int    swcnt[3];
    __shared__ double swsum[3];
    __shared__ double s_ak[8][64];
    __shared__ float  s_ae[8][64], s_ae2[8][64];
    __shared__ double s_part[2];
    __shared__ double s_rw, s_cnt;
    __shared__ int    s_m;

    int c = blockIdx.x >> 4, s = blockIdx.x & 15;
    int tid  = threadIdx.x;
    int g    = tid >> 6;          // point-group 0..7
    int lane = tid & 63;          // dim within segment
    int d    = s * 64 + lane;

    // ---- order-preserving ballot compaction over 80 candidate rows ----
    bool active = false;
    int  row_r  = 0;
    double coef_r = 0.0, lm_r = 0.0;
    int  lanepos = 0;
    if (tid < 96) {
        if (tid < 80) {
            if (tid < NSUP) { row_r = c * NSUP + tid; active = true; }
            else            { row_r = 25 + (tid - NSUP); active = (g_PRED[tid - NSUP] == c); }
            lm_r   = g_LAM[row_r];
            coef_r = lm_r * g_KFAC[row_r];
        }
        unsigned bal = __ballot_sync(0xffffffffu, active);
        lanepos = __popc(bal & ((1u << (tid & 31)) - 1u));
        double wv = active ? lm_r : 0.0;
        #pragma unroll
        for (int o = 16; o > 0; o >>= 1) wv += __shfl_down_sync(0xffffffffu, wv, o);
        if ((tid & 31) == 0) { swcnt[tid >> 5] = __popc(bal); swsum[tid >> 5] = wv; }
    }
    __syncthreads();
    if (tid == 0) {
        int m = swcnt[0] + swcnt[1] + swcnt[2];
        double wsum = swsum[0] + swsum[1] + swsum[2];
        s_rw = 1.0 / wsum; s_cnt = (double)m; s_m = m;
    }
    if (tid < 96 && active) {
        int base = (tid >= 32 ? swcnt[0] : 0) + (tid >= 64 ? swcnt[1] : 0);
        srow[base + lanepos]  = row_r;
        scoef[base + lanepos] = coef_r;
    }
    __syncthreads();
    int m = s_m;

    double ak = 0.0;
    float  ae = 0.f, ae2 = 0.f;
    #pragma unroll 4
    for (int ji = g; ji < m; ji += 8) {
        int row   = srow[ji];
        double Pv = g_P[(size_t)row * DD + d];
        float  Ev = feat[(size_t)row * DD + d];
        ak  = fma(scoef[ji], Pv, ak);
        ae  += Ev;
        ae2 = fmaf(Ev, Ev, ae2);
    }
    s_ak[g][lane] = ak; s_ae[g][lane] = ae; s_ae2[g][lane] = ae2;
    __syncthreads();

    double v = 0.0;
    if (g == 0) {   // tid < 64: warps 0,1
        double a0 = s_ak[0][lane] + s_ak[1][lane], a1 = s_ak[2][lane] + s_ak[3][lane];
        double a2 = s_ak[4][lane] + s_ak[5][lane], a3 = s_ak[6][lane] + s_ak[7][lane];
        double AK = (a0 + a1) + (a2 + a3);
        float e0 = s_ae[0][lane] + s_ae[1][lane], e1 = s_ae[2][lane] + s_ae[3][lane];
        float e2 = s_ae[4][lane] + s_ae[5][lane], e3 = s_ae[6][lane] + s_ae[7][lane];
        float AEf = (e0 + e1) + (e2 + e3);
        float q0 = s_ae2[0][lane] + s_ae2[1][lane], q1 = s_ae2[2][lane] + s_ae2[3][lane];
        float q2 = s_ae2[4][lane] + s_ae2[5][lane], q3 = s_ae2[6][lane] + s_ae2[7][lane];
        float AE2f = (q0 + q1) + (q2 + q3);
        double AE = (double)AEf, AE2 = (double)AE2f;
        double cnt = s_cnt;
        double mkd = AK * s_rw;
        g_MKD[(size_t)c * DD + d] = mkd;
        double var = fmax(AE2 - AE * AE / cnt, 0.0) / (cnt - 1.0);
        g_STD[(size_t)c * DD + d] = sqrt(var);
        v = mkd * mkd;
        // 2-warp shfl tree for mk2 partial
        #pragma unroll
        for (int o = 16; o > 0; o >>= 1) v += __shfl_down_sync(0xffffffffu, v, o);
        if ((tid & 31) == 0) s_part[tid >> 5] = v;
    }
    __syncthreads();
    if (tid == 0) g_MK2P[c * NSEGS + s] = s_part[0] + s_part[1];
}

// ---------------- K5: per (class, 2 aug-rows): pt reductions + scalar chain ----------------
// grid = 100 blocks (= 1 wave), 512 threads = 2 halves x 256. Half h handles row 2*b+h.
__global__ void __launch_bounds__(512) k_augrow(const float* __restrict__ noise) {
    __shared__ double sred[16 * 2];
    __shared__ double s_rden, s_x2sp, s_ptfac;

    int tid = threadIdx.x;
    int half = tid >> 8;           // 0 or 1
    int htid = tid & 255;          // thread within half
    int w = tid >> 5, l = tid & 31;
    int r = blockIdx.x * 2 + half; // global aug row 0..199
    int c = r / NAUG;

    if (tid == 0) {
        double mk2 = sum16(&g_MK2P[c * NSEGS]);    // pairwise tree
        double den = 1.0 + sqrt(fmax(1.0 - 0.01 * mk2, 0.0));
        s_rden  = 1.0 / den;
        double x2sp = mk2 / (den * den);
        s_x2sp  = x2sp;
        s_ptfac = 1.0 - 0.01 * x2sp;
    }
    __syncthreads();
    double rden = s_rden, x2sp = s_x2sp, ptfac = s_ptfac;

    const float* nz = noise + (size_t)r * DD;
    double a2 = 0.0, ad = 0.0;
    #pragma unroll
    for (int i = 0; i < 4; i++) {
        int dd = htid + i * 256;
        double wv = (double)nz[dd] * g_STD[(size_t)c * DD + dd];
        a2 = fma(wv, wv, a2);
        ad = fma(g_MKD[(size_t)c * DD + dd], wv, ad);
    }
    #pragma unroll
    for (int o = 16; o > 0; o >>= 1) {
        a2 += __shfl_down_sync(0xffffffffu, a2, o);
        ad += __shfl_down_sync(0xffffffffu, ad, o);
    }
    if (l == 0) { sred[w * 2] = a2; sred[w * 2 + 1] = ad; }
    __syncthreads();

    if (htid == 0) {  // tid 0 and tid 256: one scalar chain per row
        const double* sb = &sred[half * 16];
        double A2 = sum8(&sb[0], 2);
        double AD = sum8(&sb[1], 2);
        double pt2 = ptfac * ptfac * A2;
        double dxp = ptfac * rden * AD;

        double lamx = 2.0 / fmax(1.0 - 0.01 * x2sp, 1e-5);
        double un  = fmax(sqrt(pt2), 1e-5);
        double t   = tanh(0.05 * lamx * un) / (0.1 * un);
        double y2  = t * t * pt2;
        double xy  = t * dxp;
        double A   = 1.0 + 0.02 * xy + 0.01 * y2;
        double B   = ptfac * t;
        double dn  = fmax(1.0 + 0.02 * xy + 1e-4 * x2sp * y2, 1e-5);
        double idn = 1.0 / dn;
        double ex2 = (A * A * x2sp + B * B * pt2 + 2.0 * A * B * dxp) * (idn * idn);
        double kf  = 2.0 / (1.0 + 0.01 * ex2);
        double k2  = kf * kf * ex2;
        double lm  = 1.0 / sqrt(fmax(1.0 - 0.01 * k2, 1e-5));
        double lkd = lm * kf * idn;
        g_CA[r]  = lkd * A;
        g_CB[r]  = lkd * B;
        g_WL2[r] = lm;
    }
}

// ---------------- K6: refined prototype per dim (unnormalized Klein mean) ----------------
// grid = KCLS * NSEG = 40 blocks, 512 threads = 4 row-groups x 128 dims.
// Scalar sums (WL2/CA over 40+5) via 2-warp shfl tree; m2^2 via 4-warp tree.
__global__ void __launch_bounds__(512) k_newproto(const float* __restrict__ noise) {
    __shared__ double scb[NAUG], sco[NSUP];
    __shared__ double s_accN[4][128];
    __shared__ double s_pw[2], s_pa[2];
    __shared__ double s_part[4];
    __shared__ double s_rwsum2, s_SA, s_ptfac, s_rden;

    int c = blockIdx.x >> 3, s = blockIdx.x & 7;
    int tid  = threadIdx.x;
    int g    = tid >> 7;
    int lane = tid & 127;
    int d    = s * 128 + lane;

    if (tid < NAUG) scb[tid] = g_CB[c * NAUG + tid];
    if (tid >= 64 && tid < 64 + NSUP) sco[tid - 64] = g_LAM[c * NSUP + tid - 64] * g_KFAC[c * NSUP + tid - 64];

    // parallel scalar sums: weights (WL2 + support LAM) and CA, 2-warp tree
    if (tid < 64) {
        double vw = 0.0, va = 0.0;
        if (tid < NAUG)            { vw = g_WL2[c * NAUG + tid]; va = g_CA[c * NAUG + tid]; }
        else if (tid < NAUG + NSUP){ vw = g_LAM[c * NSUP + (tid - NAUG)]; }
        #pragma unroll
        for (int o = 16; o > 0; o >>= 1) {
            vw += __shfl_down_sync(0xffffffffu, vw, o);
            va += __shfl_down_sync(0xffffffffu, va, o);
        }
        if ((tid & 31) == 0) { s_pw[tid >> 5] = vw; s_pa[tid >> 5] = va; }
    }
    __syncthreads();
    if (tid == 0) {
        double mk2 = sum16(&g_MK2P[c * NSEGS]);
        double den = 1.0 + sqrt(fmax(1.0 - 0.01 * mk2, 0.0));
        double x2sp = mk2 / (den * den);
        s_rden  = 1.0 / den;
        s_ptfac = 1.0 - 0.01 * x2sp;
        s_rwsum2 = 1.0 / (s_pw[0] + s_pw[1]);
        s_SA     = s_pa[0] + s_pa[1];
    }
    __syncthreads();

    double accN = 0.0;
    #pragma unroll
    for (int ji = 0; ji < 10; ji++) {
        int j = g * 10 + ji;
        accN = fma(scb[j], (double)noise[((size_t)(c * NAUG + j)) * DD + d], accN);
    }
    s_accN[g][lane] = accN;
    __syncthreads();

    double v = 0.0;
    if (g == 0) {   // tid < 128: warps 0-3
        double acc = 0.0;
        #pragma unroll
        for (int n = 0; n < NSUP; n++)
            acc = fma(sco[n], g_P[(size_t)(c * NSUP + n) * DD + d], acc);
        double spd = g_MKD[(size_t)c * DD + d] * s_rden;
        acc += s_SA * spd;
        double AN = (s_accN[0][lane] + s_accN[1][lane]) + (s_accN[2][lane] + s_accN[3][lane]);
        acc += AN * s_ptfac * g_STD[(size_t)c * DD + d];

        double m2 = acc * s_rwsum2;
        g_M2[(size_t)c * DD + d] = m2;
        v = m2 * m2;
        #pragma unroll
        for (int o = 16; o > 0; o >>= 1) v += __shfl_down_sync(0xffffffffu, v, o);
        if ((tid & 31) == 0) s_part[tid >> 5] = v;
    }
    __syncthreads();
    if (tid == 0)
        g_MK2BP[c * NSEG + s] = (s_part[0] + s_part[1]) + (s_part[2] + s_part[3]);
}

// ---------------- K7: dist_new -> softmax y_pred; block 75 reduces loss ----------------
__global__ void k_final(float* __restrict__ out) {
    __shared__ double sred[8 * KCLS];
    __shared__ double sdots[KCLS];
    __shared__ double sden2[KCLS], sy2[KCLS];
    __shared__ double sdist[KCLS];
    __shared__ double s_max, s_sum;
    __shared__ double s_e[KCLS];
    __shared__ double sbuf[8];
    int q = blockIdx.x, tid = threadIdx.x;
    int w = tid >> 5, l = tid & 31;

    if (q == NQRY) {
        // parallel block-tree sum of 75 NLLs (was 75 serial fp64 adds)
        double v = (tid < NQRY) ? g_NLL[tid] : 0.0;
        double ssum = blk_reduce(v, sbuf, 8);
        if (tid == 0) out[NQRY * KCLS] = (float)(ssum / (double)NQRY);
        return;
    }

    if (tid < KCLS) {
        double mk2b = sum8(&g_MK2BP[tid * NSEG], 1);
        double den2 = 1.0 + sqrt(fmax(1.0 - 0.01 * mk2b, 0.0));
        sden2[tid] = den2;
        sy2[tid]   = mk2b / (den2 * den2);
    }

    int row = 25 + q;
    double p5[KCLS] = {0.0, 0.0, 0.0, 0.0, 0.0};
    #pragma unroll
    for (int i = 0; i < 4; i++) {
        int d = tid + i * 256;
        double xv = g_P[(size_t)row * DD + d];
        #pragma unroll
        for (int j = 0; j < KCLS; j++) p5[j] += xv * g_M2[(size_t)j * DD + d];
    }
    #pragma unroll
    for (int j = 0; j < KCLS; j++) {
        double v = p5[j];
        #pragma unroll
        for (int o = 16; o > 0; o >>= 1) v += __shfl_down_sync(0xffffffffu, v, o);
        if (l == 0) sred[w * KCLS + j] = v;
    }
    __syncthreads();
    if (tid < KCLS) sdots[tid] = sum8(&sred[tid], KCLS);
    __syncthreads();

    if (tid < KCLS)
        sdist[tid] = hdist(g_X2[row], sy2[tid], sdots[tid] / sden2[tid]);
    __syncthreads();

    if (tid == 0) {
        double m = -1e300;
        #pragma unroll
        for (int j = 0; j < KCLS; j++) m = fmax(m, -sdist[j]);
        s_max = m;
    }
    __syncthreads();

    if (tid < KCLS) s_e[tid] = exp(-sdist[tid] - s_max);
    __syncthreads();

    if (tid == 0)
        s_sum = ((s_e[0] + s_e[1]) + (s_e[2] + s_e[3])) + s_e[4];
    __syncthreads();

    if (tid < KCLS) out[q * KCLS + tid] = (float)(s_e[tid] / s_sum);
}

// ---------------- launch ----------------
extern "C" void kernel_launch(void* const* d_in, const int* in_sizes, int n_in,
                              void* d_out, int out_size) {
    const float* feat  = (const float*)d_in[0];
    const int*   label = (const int*)  d_in[1];
    const float* noise = (const float*)d_in[2];
    float* out = (float*)d_out;

    k_transform<<<NROWS, 256>>>(feat);
    k_proto<<<KCLS, 256>>>();
    k_dist1<<<NQRY, 256>>>(label);
    k_stats<<<KCLS * NSEGS, 512>>>(feat);
    k_augrow<<<100, 512>>>(noise);
    k_newproto<<<KCLS * NSEG, 512>>>(noise);
    k_final<<<NQRY + 1, 256>>>(out);
}

// round 14
// speedup vs baseline: 4.8589x; 1.0775x over previous
#include <cuda_runtime.h>
#include <math.h>

// Problem constants
#define DD    1024
#define KCLS  5
#define NSUP  5      // support per class
#define NQRY  75     // total queries (K*Q)
#define NAUG  40
#define NROWS 100    // 25 support + 75 queries
#define NSEGS 16     // stats: per-class dim segments (16*64 = 1024)
#define NSEG  8      // newproto: per-class dim segments (8*128 = 1024)
// hyperbolic constants: c = 0.01, sqrt(c) = 0.1

// ---------------- device scratch (static, no runtime alloc) ----------------
__device__ double g_P[NROWS * DD];       // projected Poincare points
__device__ double g_X2[NROWS];           // ||x||^2 per point
__device__ double g_KFAC[NROWS];         // 2/(1 + c||x||^2)
__device__ double g_LAM[NROWS];          // Lorentz factor of Klein point
__device__ double g_PROTO[KCLS * DD];    // initial prototypes
__device__ double g_PX2[KCLS];
__device__ int    g_PRED[NQRY];
__device__ double g_NLL[NQRY];
__device__ double g_MKD[KCLS * DD];      // masked Klein mean per dim
__device__ double g_STD[KCLS * DD];      // per-dim std of masked Euclid pts
__device__ double g_MK2P[KCLS * NSEGS];  // partial sums of mkd^2 (16/class)
__device__ double g_CA[KCLS * NAUG];     // per-aug-row coefficient on s_p
__device__ double g_CB[KCLS * NAUG];     // per-aug-row coefficient on noise
__device__ double g_WL2[KCLS * NAUG];    // per-aug-row Lorentz weight
__device__ double g_M2[KCLS * DD];       // unnormalized refined Klein mean
__device__ double g_MK2BP[KCLS * NSEG];  // partial sums of m2^2 (8/class)

// ---------------- helpers ----------------
__device__ __forceinline__ double blk_reduce(double v, double* sbuf, int nwarps) {
    #pragma unroll
    for (int o = 16; o > 0; o >>= 1) v += __shfl_down_sync(0xffffffffu, v, o);
    int w = threadIdx.x >> 5, l = threadIdx.x & 31;
    if (l == 0) sbuf[w] = v;
    __syncthreads();
    if (w == 0) {
        double r = (l < nwarps) ? sbuf[l] : 0.0;
        #pragma unroll
        for (int o = 16; o > 0; o >>= 1) r += __shfl_down_sync(0xffffffffu, r, o);
        if (l == 0) sbuf[0] = r;
    }
    __syncthreads();
    double r = sbuf[0];
    __syncthreads();
    return r;
}

// pairwise tree sums (break 47-cyc fp64 dependency chains)
__device__ __forceinline__ double sum8(const double* a, int stride) {
    double t0 = a[0] + a[stride], t1 = a[2*stride] + a[3*stride];
    double t2 = a[4*stride] + a[5*stride], t3 = a[6*stride] + a[7*stride];
    return (t0 + t1) + (t2 + t3);
}
__device__ __forceinline__ double sum16(const double* a) {
    double t0 = a[0]+a[1],   t1 = a[2]+a[3],   t2 = a[4]+a[5],   t3 = a[6]+a[7];
    double t4 = a[8]+a[9],   t5 = a[10]+a[11], t6 = a[12]+a[13], t7 = a[14]+a[15];
    return ((t0+t1)+(t2+t3)) + ((t4+t5)+(t6+t7));
}

// z of the Poincare distance: dist = 20*atanh(z); exp(-dist) = ((1-z)/(1+z))^10
__device__ __forceinline__ double hz(double x2, double y2, double xy) {
    double a    = 1.0 - 0.02 * xy + 0.01 * y2;
    double b    = 1.0 - 0.01 * x2;
    double num2 = a * a * x2 + b * b * y2 - 2.0 * a * b * xy;
    double den  = fmax(1.0 - 0.02 * xy + 1e-4 * x2 * y2, 1e-5);
    double nrm  = sqrt(fmax(num2, 0.0)) / den;
    return fmin(fmax(0.1 * nrm, -1.0 + 1e-5), 1.0 - 1e-5);
}
__device__ __forceinline__ double pow10_ratio(double z) {   // ((1-z)/(1+z))^10
    double r  = (1.0 - z) / (1.0 + z);
    double r2 = r * r, r4 = r2 * r2, r8 = r4 * r4;
    return r8 * r2;
}

// ---------------- K1: expmap0 + project + Klein scalars (100 rows) ----------------
__global__ void k_transform(const float* __restrict__ feat) {
    __shared__ double sbuf[8];
    int row = blockIdx.x, tid = threadIdx.x;
    const float* u = feat + (size_t)row * DD;
    double uv[4];
    double s2 = 0.0;
    #pragma unroll
    for (int i = 0; i < 4; i++) { uv[i] = (double)u[tid + i * 256]; s2 += uv[i] * uv[i]; }
    s2 = blk_reduce(s2, sbuf, 8);

    double nrmu = sqrt(s2);
    double un   = fmax(nrmu, 1e-5);
    double s1   = tanh(0.1 * un) / (0.1 * un);
    double e0n  = s1 * nrmu;
    double nrm  = fmax(e0n, 1e-5);
    double s    = s1;
    if (nrm > 9.99) s = s1 * (9.99 / nrm);
    double x2 = s * s * s2;

    #pragma unroll
    for (int i = 0; i < 4; i++)
        g_P[(size_t)row * DD + tid + i * 256] = s * uv[i];

    if (tid == 0) {
        g_X2[row] = x2;
        double kf = 2.0 / (1.0 + 0.01 * x2);
        double k2 = kf * kf * x2;
        g_KFAC[row] = kf;
        g_LAM[row]  = 1.0 / sqrt(fmax(1.0 - 0.01 * k2, 1e-5));
    }
}

// ---------------- K2: initial prototypes (5 classes) ----------------
__global__ void k_proto() {
    __shared__ double sco[NSUP];
    __shared__ double srw;
    __shared__ double sbuf[8];
    int c = blockIdx.x, tid = threadIdx.x;
    if (tid < NSUP) sco[tid] = g_LAM[c * NSUP + tid] * g_KFAC[c * NSUP + tid];
    if (tid == 0) {
        double w01 = g_LAM[c*NSUP] + g_LAM[c*NSUP+1];
        double w23 = g_LAM[c*NSUP+2] + g_LAM[c*NSUP+3];
        srw = 1.0 / ((w01 + w23) + g_LAM[c*NSUP+4]);
    }
    __syncthreads();
    double rwsum = srw;

    double mk[4]; double part = 0.0;
    #pragma unroll
    for (int i = 0; i < 4; i++) {
        int d = tid + i * 256;
        double a = 0.0;
        #pragma unroll
        for (int n = 0; n < NSUP; n++) a += sco[n] * g_P[(size_t)(c * NSUP + n) * DD + d];
        mk[i] = a * rwsum;
        part += mk[i] * mk[i];
    }
    double mk2 = blk_reduce(part, sbuf, 8);
    double den = 1.0 + sqrt(fmax(1.0 - 0.01 * mk2, 0.0));   // k2p
    double rden = 1.0 / den;
    #pragma unroll
    for (int i = 0; i < 4; i++)
        g_PROTO[(size_t)c * DD + tid + i * 256] = mk[i] * rden;
    if (tid == 0) g_PX2[c] = mk2 / (den * den);
}

// ---------------- K3: dist matrix, argmin pred, per-query NLL (75 queries) ----------------
// pred = argmax(-dist) = argmin dist = argmin z (dist monotone increasing in z).
// NLL = log(sum_j w_j / w_lbl), w = ((1-z)/(1+z))^10 = exp(-dist).
__global__ void k_dist1(const int* __restrict__ label) {
    __shared__ double sred[8 * KCLS];
    __shared__ double sdots[KCLS];
    __shared__ double s_px2[KCLS];
    __shared__ double s_z[KCLS], s_w[KCLS];
    int q = blockIdx.x, tid = threadIdx.x;
    int row = 25 + q;
    int w = tid >> 5, l = tid & 31;

    if (tid < KCLS) s_px2[tid] = g_PX2[tid];   // prefetch
    double x2 = g_X2[row];                     // prefetch (broadcast)

    double p5[KCLS] = {0.0, 0.0, 0.0, 0.0, 0.0};
    #pragma unroll
    for (int i = 0; i < 4; i++) {
        int d = tid + i * 256;
        double xv = g_P[(size_t)row * DD + d];
        #pragma unroll
        for (int j = 0; j < KCLS; j++) p5[j] += xv * g_PROTO[(size_t)j * DD + d];
    }
    #pragma unroll
    for (int j = 0; j < KCLS; j++) {
        double v = p5[j];
        #pragma unroll
        for (int o = 16; o > 0; o >>= 1) v += __shfl_down_sync(0xffffffffu, v, o);
        if (l == 0) sred[w * KCLS + j] = v;
    }
    __syncthreads();
    if (tid < KCLS) sdots[tid] = sum8(&sred[tid], KCLS);   // pairwise over 8 warps
    __syncthreads();

    if (tid < 32) {   // warp 0 tail only
        if (tid < KCLS) {
            double zv = hz(x2, s_px2[tid], sdots[tid]);
            s_z[tid] = zv;
            s_w[tid] = pow10_ratio(zv);   // = exp(-dist)
        }
        __syncwarp();
        if (tid == 0) {
            // argmin z == argmin dist == argmax(-dist); strict < keeps first-tie semantics
            int best = 0; double bz = s_z[0];
            #pragma unroll
            for (int j = 1; j < KCLS; j++) if (s_z[j] < bz) { bz = s_z[j]; best = j; }
            g_PRED[q] = best;
            double sw = ((s_w[0] + s_w[1]) + (s_w[2] + s_w[3])) + s_w[4];
            int lbl = label[NQRY + q];
            g_NLL[q] = log(sw / s_w[lbl]);   // = lse + dist[lbl]
        }
    }
}

// ---------------- K4: per-class per-dim masked Klein mean + Euclid std ----------------
// grid = KCLS * NSEGS = 80 blocks, 512 threads = 8 point-groups x 64 dims.
__global__ void __launch_bounds__(512) k_stats(const float* __restrict__ feat) {
    __shared__ double scoef[80];
    __shared__ int    srow[80];
    __shared__ int    swcnt[3];
    __shared__ double swsum[3];
    __shared__ double s_ak[8][64];
    __shared__ float  s_ae[8][64], s_ae2[8][64];
    __shared__ double s_part[2];
    __shared__ double s_rw, s_cnt;
    __shared__ int    s_m;

    int c = blockIdx.x >> 4, s = blockIdx.x & 15;
    int tid  = threadIdx.x;
    int g    = tid >> 6;          // point-group 0..7
    int lane = tid & 63;          // dim within segment
    int d    = s * 64 + lane;

    // ---- order-preserving ballot compaction over 80 candidate rows ----
    bool active = false;
    int  row_r  = 0;
    double coef_r = 0.0, lm_r = 0.0;
    int  lanepos = 0;
    if (tid < 96) {
        if (tid < 80) {
            if (tid < NSUP) { row_r = c * NSUP + tid; active = true; }
            else            { row_r = 25 + (tid - NSUP); active = (g_PRED[tid - NSUP] == c); }
            lm_r   = g_LAM[row_r];
            coef_r = lm_r * g_KFAC[row_r];
        }
        unsigned bal = __ballot_sync(0xffffffffu, active);
        lanepos = __popc(bal & ((1u << (tid & 31)) - 1u));
        double wv = active ? lm_r : 0.0;
        #pragma unroll
        for (int o = 16; o > 0; o >>= 1) wv += __shfl_down_sync(0xffffffffu, wv, o);
        if ((tid & 31) == 0) { swcnt[tid >> 5] = __popc(bal); swsum[tid >> 5] = wv; }
    }
    __syncthreads();
    if (tid == 0) {
        int m = swcnt[0] + swcnt[1] + swcnt[2];
        double wsum = swsum[0] + swsum[1] + swsum[2];
        s_rw = 1.0 / wsum; s_cnt = (double)m; s_m = m;
    }
    if (tid < 96 && active) {
        int base = (tid >= 32 ? swcnt[0] : 0) + (tid >= 64 ? swcnt[1] : 0);
        srow[base + lanepos]  = row_r;
        scoef[base + lanepos] = coef_r;
    }
    __syncthreads();
    int m = s_m;

    double ak = 0.0;
    float  ae = 0.f, ae2 = 0.f;
    #pragma unroll 4
    for (int ji = g; ji < m; ji += 8) {
        int row   = srow[ji];
        double Pv = g_P[(size_t)row * DD + d];
        float  Ev = feat[(size_t)row * DD + d];
        ak  = fma(scoef[ji], Pv, ak);
        ae  += Ev;
        ae2 = fmaf(Ev, Ev, ae2);
    }
    s_ak[g][lane] = ak; s_ae[g][lane] = ae; s_ae2[g][lane] = ae2;
    __syncthreads();

    double v = 0.0;
    if (g == 0) {   // tid < 64: warps 0,1
        double a0 = s_ak[0][lane] + s_ak[1][lane], a1 = s_ak[2][lane] + s_ak[3][lane];
        double a2 = s_ak[4][lane] + s_ak[5][lane], a3 = s_ak[6][lane] + s_ak[7][lane];
        double AK = (a0 + a1) + (a2 + a3);
        float e0 = s_ae[0][lane] + s_ae[1][lane], e1 = s_ae[2][lane] + s_ae[3][lane];
        float e2 = s_ae[4][lane] + s_ae[5][lane], e3 = s_ae[6][lane] + s_ae[7][lane];
        float AEf = (e0 + e1) + (e2 + e3);
        float q0 = s_ae2[0][lane] + s_ae2[1][lane], q1 = s_ae2[2][lane] + s_ae2[3][lane];
        float q2 = s_ae2[4][lane] + s_ae2[5][lane], q3 = s_ae2[6][lane] + s_ae2[7][lane];
        float AE2f = (q0 + q1) + (q2 + q3);
        double AE = (double)AEf, AE2 = (double)AE2f;
        double cnt = s_cnt;
        double mkd = AK * s_rw;
        g_MKD[(size_t)c * DD + d] = mkd;
        double var = fmax(AE2 - AE * AE / cnt, 0.0) / (cnt - 1.0);
        g_STD[(size_t)c * DD + d] = sqrt(var);
        v = mkd * mkd;
        #pragma unroll
        for (int o = 16; o > 0; o >>= 1) v += __shfl_down_sync(0xffffffffu, v, o);
        if ((tid & 31) == 0) s_part[tid >> 5] = v;
    }
    __syncthreads();
    if (tid == 0) g_MK2P[c * NSEGS + s] = s_part[0] + s_part[1];
}

// ---------------- K5: per (class, 2 aug-rows): pt reductions + scalar chain ----------------
// grid = 100 blocks (= 1 wave), 512 threads = 2 halves x 256. Half h handles row 2*b+h.
__global__ void __launch_bounds__(512) k_augrow(const float* __restrict__ noise) {
    __shared__ double sred[16 * 2];
    __shared__ double s_rden, s_x2sp, s_ptfac;

    int tid = threadIdx.x;
    int half = tid >> 8;           // 0 or 1
    int htid = tid & 255;          // thread within half
    int w = tid >> 5, l = tid & 31;
    int r = blockIdx.x * 2 + half; // global aug row 0..199
    int c = r / NAUG;

    if (tid == 0) {
        double mk2 = sum16(&g_MK2P[c * NSEGS]);    // pairwise tree
        double den = 1.0 + sqrt(fmax(1.0 - 0.01 * mk2, 0.0));
        s_rden  = 1.0 / den;
        double x2sp = mk2 / (den * den);
        s_x2sp  = x2sp;
        s_ptfac = 1.0 - 0.01 * x2sp;
    }
    __syncthreads();
    double rden = s_rden, x2sp = s_x2sp, ptfac = s_ptfac;

    const float* nz = noise + (size_t)r * DD;
    double a2 = 0.0, ad = 0.0;
    #pragma unroll
    for (int i = 0; i < 4; i++) {
        int dd = htid + i * 256;
        double wv = (double)nz[dd] * g_STD[(size_t)c * DD + dd];
        a2 = fma(wv, wv, a2);
        ad = fma(g_MKD[(size_t)c * DD + dd], wv, ad);
    }
    #pragma unroll
    for (int o = 16; o > 0; o >>= 1) {
        a2 += __shfl_down_sync(0xffffffffu, a2, o);
        ad += __shfl_down_sync(0xffffffffu, ad, o);
    }
    if (l == 0) { sred[w * 2] = a2; sred[w * 2 + 1] = ad; }
    __syncthreads();

    if (htid == 0) {  // tid 0 and tid 256: one scalar chain per row
        const double* sb = &sred[half * 16];
        double A2 = sum8(&sb[0], 2);
        double AD = sum8(&sb[1], 2);
        double pt2 = ptfac * ptfac * A2;
        double dxp = ptfac * rden * AD;

        double lamx = 2.0 / fmax(1.0 - 0.01 * x2sp, 1e-5);
        double un  = fmax(sqrt(pt2), 1e-5);
        double t   = tanh(0.05 * lamx * un) / (0.1 * un);
        double y2  = t * t * pt2;
        double xy  = t * dxp;
        double A   = 1.0 + 0.02 * xy + 0.01 * y2;
        double B   = ptfac * t;
        double dn  = fmax(1.0 + 0.02 * xy + 1e-4 * x2sp * y2, 1e-5);
        double idn = 1.0 / dn;
        double ex2 = (A * A * x2sp + B * B * pt2 + 2.0 * A * B * dxp) * (idn * idn);
        double kf  = 2.0 / (1.0 + 0.01 * ex2);
        double k2  = kf * kf * ex2;
        double lm  = 1.0 / sqrt(fmax(1.0 - 0.01 * k2, 1e-5));
        double lkd = lm * kf * idn;
        g_CA[r]  = lkd * A;
        g_CB[r]  = lkd * B;
        g_WL2[r] = lm;
    }
}

// ---------------- K6: refined prototype per dim (unnormalized Klein mean) ----------------
// grid = KCLS * NSEG = 40 blocks, 512 threads = 4 row-groups x 128 dims.
__global__ void __launch_bounds__(512) k_newproto(const float* __restrict__ noise) {
    __shared__ double scb[NAUG], sco[NSUP];
    __shared__ double s_accN[4][128];
    __shared__ double s_pw[2], s_pa[2];
    __shared__ double s_part[4];
    __shared__ double s_rwsum2, s_SA, s_ptfac, s_rden;

    int c = blockIdx.x >> 3, s = blockIdx.x & 7;
    int tid  = threadIdx.x;
    int g    = tid >> 7;
    int lane = tid & 127;
    int d    = s * 128 + lane;

    if (tid < NAUG) scb[tid] = g_CB[c * NAUG + tid];
    if (tid >= 64 && tid < 64 + NSUP) sco[tid - 64] = g_LAM[c * NSUP + tid - 64] * g_KFAC[c * NSUP + tid - 64];

    // parallel scalar sums: weights (WL2 + support LAM) and CA, 2-warp tree
    if (tid < 64) {
        double vw = 0.0, va = 0.0;
        if (tid < NAUG)            { vw = g_WL2[c * NAUG + tid]; va = g_CA[c * NAUG + tid]; }
        else if (tid < NAUG + NSUP){ vw = g_LAM[c * NSUP + (tid - NAUG)]; }
        #pragma unroll
        for (int o = 16; o > 0; o >>= 1) {
            vw += __shfl_down_sync(0xffffffffu, vw, o);
            va += __shfl_down_sync(0xffffffffu, va, o);
        }
        if ((tid & 31) == 0) { s_pw[tid >> 5] = vw; s_pa[tid >> 5] = va; }
    }
    __syncthreads();
    if (tid == 0) {
        double mk2 = sum16(&g_MK2P[c * NSEGS]);
        double den = 1.0 + sqrt(fmax(1.0 - 0.01 * mk2, 0.0));
        double x2sp = mk2 / (den * den);
        s_rden  = 1.0 / den;
        s_ptfac = 1.0 - 0.01 * x2sp;
        s_rwsum2 = 1.0 / (s_pw[0] + s_pw[1]);
        s_SA     = s_pa[0] + s_pa[1];
    }
    __syncthreads();

    double accN = 0.0;
    #pragma unroll
    for (int ji = 0; ji < 10; ji++) {
        int j = g * 10 + ji;
        accN = fma(scb[j], (double)noise[((size_t)(c * NAUG + j)) * DD + d], accN);
    }
    s_accN[g][lane] = accN;
    __syncthreads();

    double v = 0.0;
    if (g == 0) {   // tid < 128: warps 0-3
        double acc = 0.0;
        #pragma unroll
        for (int n = 0; n < NSUP; n++)
            acc = fma(sco[n], g_P[(size_t)(c * NSUP + n) * DD + d], acc);
        double spd = g_MKD[(size_t)c * DD + d] * s_rden;
        acc += s_SA * spd;
        double AN = (s_accN[0][lane] + s_accN[1][lane]) + (s_accN[2][lane] + s_accN[3][lane]);
        acc += AN * s_ptfac * g_STD[(size_t)c * DD + d];

        double m2 = acc * s_rwsum2;
        g_M2[(size_t)c * DD + d] = m2;
        v = m2 * m2;
        #pragma unroll
        for (int o = 16; o > 0; o >>= 1) v += __shfl_down_sync(0xffffffffu, v, o);
        if ((tid & 31) == 0) s_part[tid >> 5] = v;
    }
    __syncthreads();
    if (tid == 0)
        g_MK2BP[c * NSEG + s] = (s_part[0] + s_part[1]) + (s_part[2] + s_part[3]);
}

// ---------------- K7: dist_new -> softmax y_pred; block 75 reduces loss ----------------
// softmax(-dist) = w_j / sum w_j with w = ((1-z)/(1+z))^10 — zero transcendentals.
__global__ void k_final(float* __restrict__ out) {
    __shared__ double sred[8 * KCLS];
    __shared__ double sdots[KCLS];
    __shared__ double sden2[KCLS], sy2[KCLS];
    __shared__ double s_w[KCLS];
    __shared__ double s_sum;
    __shared__ double sbuf[8];
    int q = blockIdx.x, tid = threadIdx.x;
    int w = tid >> 5, l = tid & 31;

    if (q == NQRY) {
        // parallel block-tree sum of 75 NLLs
        double v = (tid < NQRY) ? g_NLL[tid] : 0.0;
        double ssum = blk_reduce(v, sbuf, 8);
        if (tid == 0) out[NQRY * KCLS] = (float)(ssum / (double)NQRY);
        return;
    }

    if (tid < KCLS) {
        double mk2b = sum8(&g_MK2BP[tid * NSEG], 1);
        double den2 = 1.0 + sqrt(fmax(1.0 - 0.01 * mk2b, 0.0));
        sden2[tid] = den2;
        sy2[tid]   = mk2b / (den2 * den2);
    }
    int row = 25 + q;
    double x2 = g_X2[row];     // prefetch (broadcast)

    double p5[KCLS] = {0.0, 0.0, 0.0, 0.0, 0.0};
    #pragma unroll
    for (int i = 0; i < 4; i++) {
        int d = tid + i * 256;
        double xv = g_P[(size_t)row * DD + d];
        #pragma unroll
        for (int j = 0; j < KCLS; j++) p5[j] += xv * g_M2[(size_t)j * DD + d];
    }
    #pragma unroll
    for (int j = 0; j < KCLS; j++) {
        double v = p5[j];
        #pragma unroll
        for (int o = 16; o > 0; o >>= 1) v += __shfl_down_sync(0xffffffffu, v, o);
        if (l == 0) sred[w * KCLS + j] = v;
    }
    __syncthreads();
    if (tid < KCLS) sdots[tid] = sum8(&sred[tid], KCLS);
    __syncthreads();

    if (tid < 32) {   // warp 0 tail only
        if (tid < KCLS) {
            double zv = hz(x2, sy2[tid], sdots[tid] / sden2[tid]);
            s_w[tid] = pow10_ratio(zv);   // = exp(-dist)
        }
        __syncwarp();
        if (tid == 0)
            s_sum = ((s_w[0] + s_w[1]) + (s_w[2] + s_w[3])) + s_w[4];
        __syncwarp();
        if (tid < KCLS) out[q * KCLS + tid] = (float)(s_w[tid] / s_sum);
    }
}

// ---------------- launch ----------------
extern "C" void kernel_launch(void* const* d_in, const int* in_sizes, int n_in,
                              void* d_out, int out_size) {
    const float* feat  = (const float*)d_in[0];
    const int*   label = (const int*)  d_in[1];
    const float* noise = (const float*)d_in[2];
    float* out = (float*)d_out;

    k_transform<<<NROWS, 256>>>(feat);
    k_proto<<<KCLS, 256>>>();
    k_dist1<<<NQRY, 256>>>(label);
    k_stats<<<KCLS * NSEGS, 512>>>(feat);
    k_augrow<<<100, 512>>>(noise);
    k_newproto<<<KCLS * NSEG, 512>>>(noise);
    k_final<<<NQRY + 1, 256>>>(out);
}